// round 1
// baseline (speedup 1.0000x reference)
#include <cuda_runtime.h>
#include <math.h>

#define Bz 8
#define Sz 4096
#define Dz 512
#define Mz (Bz * Sz)          // 32768 rows
#define D4 (4 * Dz)           // 2048
#define D2 (2 * Dz)           // 1024

// ---------------- scratch (static device globals; no allocation) ----------------
__device__ float g_omega[Mz * Dz];
__device__ float g_mag  [Mz * Dz];
__device__ float g_gate [Mz * Dz];
__device__ float g_qoff [Mz * Dz];
__device__ float g_p1h  [Mz * Dz];
__device__ float g_phii [Mz * Dz];
__device__ float g_ctx  [(size_t)Mz * D4];
__device__ float g_h    [(size_t)Mz * D2];

// ---------------- GEMM: C[M,N] = epi(A[M,K] @ W[K,N] + bias[N]) ----------------
// EPI: 0 = none, 1 = exact gelu, 2 = sigmoid, 3 = sigmoid*5, 4 = + resid
#define BM 128
#define BN 128
#define BKk 8
#define TM 8
#define TN 8

template <int EPI>
__global__ __launch_bounds__(256, 2)
void gemm_kernel(const float* __restrict__ A, const float* __restrict__ W,
                 const float* __restrict__ bias, float* __restrict__ C,
                 int M, int N, int K, const float* __restrict__ resid)
{
    __shared__ float As[BKk][BM];
    __shared__ float Bs[BKk][BN];

    const int tid  = threadIdx.x;
    const int bm   = blockIdx.y;
    const int bn   = blockIdx.x;
    const int trow = tid >> 4;        // 0..15
    const int tcol = tid & 15;        // 0..15

    const int arow = tid >> 1;        // 0..127
    const int acol = (tid & 1) * 4;   // 0 or 4
    const int brow = tid >> 5;        // 0..7
    const int bcol = (tid & 31) * 4;  // 0..124

    const float* Ab = A + (size_t)bm * BM * K;
    const float* Wb = W + (size_t)bn * BN;

    float acc[TM][TN];
#pragma unroll
    for (int i = 0; i < TM; i++)
#pragma unroll
        for (int j = 0; j < TN; j++) acc[i][j] = 0.f;

    for (int k0 = 0; k0 < K; k0 += BKk) {
        float4 av = *(const float4*)(Ab + (size_t)arow * K + k0 + acol);
        As[acol + 0][arow] = av.x;
        As[acol + 1][arow] = av.y;
        As[acol + 2][arow] = av.z;
        As[acol + 3][arow] = av.w;
        float4 bv = *(const float4*)(Wb + (size_t)(k0 + brow) * N + bcol);
        *(float4*)&Bs[brow][bcol] = bv;
        __syncthreads();

#pragma unroll
        for (int k = 0; k < BKk; k++) {
            float ra[TM], rb[TN];
            *(float4*)&ra[0] = *(const float4*)&As[k][trow * TM + 0];
            *(float4*)&ra[4] = *(const float4*)&As[k][trow * TM + 4];
            *(float4*)&rb[0] = *(const float4*)&Bs[k][tcol * TN + 0];
            *(float4*)&rb[4] = *(const float4*)&Bs[k][tcol * TN + 4];
#pragma unroll
            for (int i = 0; i < TM; i++)
#pragma unroll
                for (int j = 0; j < TN; j++) acc[i][j] += ra[i] * rb[j];
        }
        __syncthreads();
    }

#pragma unroll
    for (int i = 0; i < TM; i++) {
        const int row = bm * BM + trow * TM + i;
#pragma unroll
        for (int j = 0; j < TN; j++) {
            const int col = bn * BN + tcol * TN + j;
            float v = acc[i][j] + bias[col];
            if (EPI == 1) {                      // exact gelu
                v = 0.5f * v * (1.0f + erff(v * 0.70710678118654752f));
            } else if (EPI == 2) {               // sigmoid
                v = 1.0f / (1.0f + expf(-v));
            } else if (EPI == 3) {               // sigmoid * 5
                v = 5.0f / (1.0f + expf(-v));
            } else if (EPI == 4) {               // + residual
                v += resid[(size_t)row * N + col];
            }
            C[(size_t)row * N + col] = v;
        }
    }
}

// ---------------- scan kernel: one thread per (b,d) channel ----------------
__global__ void scan_kernel(const float* __restrict__ x,
                            const float* __restrict__ omega,
                            const float* __restrict__ gate,
                            const float* __restrict__ mag,
                            const float* __restrict__ phii,
                            const float* __restrict__ qoff,
                            const float* __restrict__ iscale,
                            float* __restrict__ ctx)
{
    const int b = blockIdx.y;
    const int d = blockIdx.x * 32 + threadIdx.x;
    const float isc = fabsf(iscale[d]);

    size_t base  = ((size_t)b * Sz) * Dz + d;
    size_t cbase = ((size_t)b * Sz) * D4 + d;

    float phic = 0.f, mr = 0.f, mi = 0.f, cm = 0.f;

    // software-pipelined loads (loads of s+1 are independent of the carries)
    size_t idx = base;
    float o  = omega[idx], g = gate[idx], m = mag[idx];
    float xi = x[idx],     pi = phii[idx], qo = qoff[idx];

    for (int s = 0; s < Sz; ++s) {
        float o_n, g_n, m_n, xi_n, pi_n, qo_n;
        if (s + 1 < Sz) {
            size_t idx2 = idx + Dz;
            o_n = omega[idx2]; g_n = gate[idx2]; m_n = mag[idx2];
            xi_n = x[idx2];    pi_n = phii[idx2]; qo_n = qoff[idx2];
        } else {
            o_n = g_n = m_n = xi_n = pi_n = qo_n = 0.f;
        }

        phic += g * o * isc;
        float phi = pi + phic;
        float c, sn;
        sincosf(phi, &sn, &c);
        float wc = m * xi;
        mr += wc * c;
        mi += wc * sn;
        cm += m;
        float r   = 1.0f / sqrtf(cm + 1e-8f);
        float mrn = mr * r;
        float min_ = mi * r;
        float cq, sq;
        sincosf(phi + qo, &sq, &cq);

        size_t ci = cbase + (size_t)s * D4;
        ctx[ci]          = xi * c;
        ctx[ci + Dz]     = xi * sn;
        ctx[ci + 2 * Dz] = mrn * cq + min_ * sq;
        ctx[ci + 3 * Dz] = min_ * cq - mrn * sq;

        o = o_n; g = g_n; m = m_n; xi = xi_n; pi = pi_n; qo = qo_n;
        idx += Dz;
    }
}

// ---------------- layernorm (in-place), dim = 2048 ----------------
__device__ __forceinline__ float block_reduce_sum(float val)
{
    __shared__ float sh[8];
    int lane = threadIdx.x & 31, w = threadIdx.x >> 5;
    __syncthreads();   // protect sh reuse across successive calls
#pragma unroll
    for (int o = 16; o > 0; o >>= 1) val += __shfl_down_sync(0xffffffffu, val, o);
    if (lane == 0) sh[w] = val;
    __syncthreads();
    if (w == 0) {
        val = (lane < 8) ? sh[lane] : 0.f;
#pragma unroll
        for (int o = 4; o > 0; o >>= 1) val += __shfl_down_sync(0xffffffffu, val, o);
        if (lane == 0) sh[0] = val;
    }
    __syncthreads();
    return sh[0];
}

__global__ __launch_bounds__(256)
void ln_kernel(float* __restrict__ ctx, const float* __restrict__ gamma,
               const float* __restrict__ beta)
{
    const int row = blockIdx.x;
    float* p = ctx + (size_t)row * D4;
    const int t = threadIdx.x;

    float v[8];
    float sum = 0.f;
#pragma unroll
    for (int i = 0; i < 8; i++) {
        v[i] = p[t + 256 * i];
        sum += v[i];
    }
    sum = block_reduce_sum(sum);
    const float mean = sum * (1.0f / (float)D4);

    float sq = 0.f;
#pragma unroll
    for (int i = 0; i < 8; i++) {
        float dv = v[i] - mean;
        sq += dv * dv;
    }
    sq = block_reduce_sum(sq);
    const float var  = sq * (1.0f / (float)D4);
    const float rstd = 1.0f / sqrtf(var + 1e-5f);

#pragma unroll
    for (int i = 0; i < 8; i++) {
        const int col = t + 256 * i;
        p[col] = (v[i] - mean) * rstd * gamma[col] + beta[col];
    }
}

// ---------------- launch ----------------
extern "C" void kernel_launch(void* const* d_in, const int* in_sizes, int n_in,
                              void* d_out, int out_size)
{
    const float* x       = (const float*)d_in[0];
    const float* W_omega = (const float*)d_in[1];
    const float* b_omega = (const float*)d_in[2];
    const float* W_p1    = (const float*)d_in[3];
    const float* b_p1    = (const float*)d_in[4];
    const float* W_p2    = (const float*)d_in[5];
    const float* b_p2    = (const float*)d_in[6];
    const float* W_gate  = (const float*)d_in[7];
    const float* b_gate  = (const float*)d_in[8];
    const float* iscale  = (const float*)d_in[9];
    const float* W_mag   = (const float*)d_in[10];
    const float* b_mag   = (const float*)d_in[11];
    const float* W_qoff  = (const float*)d_in[12];
    const float* b_qoff  = (const float*)d_in[13];
    const float* ln_g    = (const float*)d_in[14];
    const float* ln_b    = (const float*)d_in[15];
    const float* W_o1    = (const float*)d_in[16];
    const float* b_o1    = (const float*)d_in[17];
    const float* W_o2    = (const float*)d_in[18];
    const float* b_o2    = (const float*)d_in[19];
    float* out = (float*)d_out;

    float *p_omega, *p_mag, *p_gate, *p_qoff, *p_p1h, *p_phii, *p_ctx, *p_h;
    cudaGetSymbolAddress((void**)&p_omega, g_omega);
    cudaGetSymbolAddress((void**)&p_mag,   g_mag);
    cudaGetSymbolAddress((void**)&p_gate,  g_gate);
    cudaGetSymbolAddress((void**)&p_qoff,  g_qoff);
    cudaGetSymbolAddress((void**)&p_p1h,   g_p1h);
    cudaGetSymbolAddress((void**)&p_phii,  g_phii);
    cudaGetSymbolAddress((void**)&p_ctx,   g_ctx);
    cudaGetSymbolAddress((void**)&p_h,     g_h);

    dim3 blk(256);
    dim3 grdD(Dz / BN, Mz / BM);    // N=512
    dim3 grd2(D2 / BN, Mz / BM);    // N=1024

    // projections from x
    gemm_kernel<0><<<grdD, blk>>>(x, W_omega, b_omega, p_omega, Mz, Dz, Dz, nullptr);
    gemm_kernel<3><<<grdD, blk>>>(x, W_mag,   b_mag,   p_mag,   Mz, Dz, Dz, nullptr);
    gemm_kernel<2><<<grdD, blk>>>(x, W_gate,  b_gate,  p_gate,  Mz, Dz, Dz, nullptr);
    gemm_kernel<0><<<grdD, blk>>>(x, W_qoff,  b_qoff,  p_qoff,  Mz, Dz, Dz, nullptr);
    gemm_kernel<1><<<grdD, blk>>>(x, W_p1,    b_p1,    p_p1h,   Mz, Dz, Dz, nullptr);
    gemm_kernel<0><<<grdD, blk>>>(p_p1h, W_p2, b_p2,   p_phii,  Mz, Dz, Dz, nullptr);

    // sequential scan over S, builds context [Mz, 2048]
    dim3 sgrid(Dz / 32, Bz);
    scan_kernel<<<sgrid, 32>>>(x, p_omega, p_gate, p_mag, p_phii, p_qoff, iscale, p_ctx);

    // layernorm in place
    ln_kernel<<<Mz, 256>>>(p_ctx, ln_g, ln_b);

    // output MLP
    gemm_kernel<1><<<grd2, blk>>>(p_ctx, W_o1, b_o1, p_h, Mz, D2, D4, nullptr);
    gemm_kernel<4><<<grdD, blk>>>(p_h,   W_o2, b_o2, out, Mz, Dz, D2, x);
}

// round 3
// speedup vs baseline: 1.7578x; 1.7578x over previous
#include <cuda_runtime.h>
#include <cuda_bf16.h>
#include <math.h>
#include <stdint.h>

#define Bz 8
#define Sz 4096
#define Dz 512
#define Mz (Bz * Sz)          // 32768 rows
#define D4 (4 * Dz)           // 2048
#define D2 (2 * Dz)           // 1024

// ---------------------------------------------------------------------------
// Scratch (static device globals; no allocation)
// ---------------------------------------------------------------------------
__device__ float g_omega[(size_t)Mz * Dz];
__device__ float g_mag  [(size_t)Mz * Dz];
__device__ float g_gate [(size_t)Mz * Dz];
__device__ float g_qoff [(size_t)Mz * Dz];
__device__ float g_p1h  [(size_t)Mz * Dz];
__device__ float g_phii [(size_t)Mz * Dz];
__device__ float g_ctx  [(size_t)Mz * D4];
__device__ float g_h    [(size_t)Mz * D2];

// packed bf16 hi/lo activations (SW128 tile-blocked layout)
__device__ __nv_bfloat16 g_xp_h [(size_t)Mz * Dz];
__device__ __nv_bfloat16 g_xp_l [(size_t)Mz * Dz];
__device__ __nv_bfloat16 g_p1p_h[(size_t)Mz * Dz];
__device__ __nv_bfloat16 g_p1p_l[(size_t)Mz * Dz];
__device__ __nv_bfloat16 g_ctxp_h[(size_t)Mz * D4];
__device__ __nv_bfloat16 g_ctxp_l[(size_t)Mz * D4];
__device__ __nv_bfloat16 g_hp_h [(size_t)Mz * D2];
__device__ __nv_bfloat16 g_hp_l [(size_t)Mz * D2];

// packed bf16 hi/lo weights (transposed to [N,K], SW128 tile-blocked)
__device__ __nv_bfloat16 g_wom_h[Dz * Dz],  g_wom_l[Dz * Dz];
__device__ __nv_bfloat16 g_wp1_h[Dz * Dz],  g_wp1_l[Dz * Dz];
__device__ __nv_bfloat16 g_wp2_h[Dz * Dz],  g_wp2_l[Dz * Dz];
__device__ __nv_bfloat16 g_wgt_h[Dz * Dz],  g_wgt_l[Dz * Dz];
__device__ __nv_bfloat16 g_wmg_h[Dz * Dz],  g_wmg_l[Dz * Dz];
__device__ __nv_bfloat16 g_wqo_h[Dz * Dz],  g_wqo_l[Dz * Dz];
__device__ __nv_bfloat16 g_wo1_h[(size_t)D4 * D2],  g_wo1_l[(size_t)D4 * D2];
__device__ __nv_bfloat16 g_wo2_h[D2 * Dz],  g_wo2_l[D2 * Dz];

// ---------------------------------------------------------------------------
// PTX helpers (sm_80-compatible subset only: cp.async, ldmatrix, mma.sync)
// ---------------------------------------------------------------------------
__device__ __forceinline__ uint32_t smem_u32(const void* p) {
    uint32_t a;
    asm("{ .reg .u64 t; cvta.to.shared.u64 t, %1; cvt.u32.u64 %0, t; }" : "=r"(a) : "l"(p));
    return a;
}

__device__ __forceinline__ void cp16(uint32_t dst, const void* src) {
    asm volatile("cp.async.cg.shared.global [%0], [%1], 16;" :: "r"(dst), "l"(src));
}
#define CP_COMMIT() asm volatile("cp.async.commit_group;" ::: "memory")
#define CP_WAIT(n)  asm volatile("cp.async.wait_group %0;" :: "n"(n) : "memory")

__device__ __forceinline__ void ldsm4(uint32_t* r, uint32_t addr) {
    asm volatile("ldmatrix.sync.aligned.m8n8.x4.shared.b16 {%0,%1,%2,%3}, [%4];"
                 : "=r"(r[0]), "=r"(r[1]), "=r"(r[2]), "=r"(r[3]) : "r"(addr));
}

__device__ __forceinline__ void mma16816(float* d, const uint32_t* a, uint32_t b0, uint32_t b1) {
    asm volatile(
        "mma.sync.aligned.m16n8k16.row.col.f32.bf16.bf16.f32 "
        "{%0,%1,%2,%3}, {%4,%5,%6,%7}, {%8,%9}, {%0,%1,%2,%3};"
        : "+f"(d[0]), "+f"(d[1]), "+f"(d[2]), "+f"(d[3])
        : "r"(a[0]), "r"(a[1]), "r"(a[2]), "r"(a[3]), "r"(b0), "r"(b1));
}

__device__ __forceinline__ uint32_t sw128(uint32_t b) { return b ^ ((b >> 3) & 0x70); }

// ---------------------------------------------------------------------------
// Packing kernels: fp32 -> bf16 hi/lo in SW128 tile-blocked layout.
// Block (mtile, chunk) = 16KB: 128 rows x 128B (64 bf16 of K), swizzled.
// ---------------------------------------------------------------------------
__global__ void pack_a_kernel(const float* __restrict__ A,
                              __nv_bfloat16* __restrict__ Ph,
                              __nv_bfloat16* __restrict__ Pl,
                              int K, long total8)
{
    long idx = (long)blockIdx.x * blockDim.x + threadIdx.x;
    if (idx >= total8) return;
    int kk8 = K >> 3;
    int row = (int)(idx / kk8);
    int k   = (int)(idx % kk8) << 3;

    const float4* p = (const float4*)(A + (size_t)row * K + k);
    float4 a = p[0], b = p[1];
    float v[8] = {a.x, a.y, a.z, a.w, b.x, b.y, b.z, b.w};

    __align__(16) __nv_bfloat16 hi[8], lo[8];
#pragma unroll
    for (int i = 0; i < 8; i++) {
        hi[i] = __float2bfloat16(v[i]);
        lo[i] = __float2bfloat16(v[i] - __bfloat162float(hi[i]));
    }

    int mt = row >> 7, r = row & 127, ch = k >> 6, c = k & 63;
    size_t blk = (size_t)mt * (K >> 6) + ch;
    uint32_t sw = sw128((uint32_t)(r * 128 + c * 2));
    size_t off = blk * 16384 + sw;   // bytes
    *(uint4*)((char*)Ph + off) = *(const uint4*)hi;
    *(uint4*)((char*)Pl + off) = *(const uint4*)lo;
}

// weights: fp32 W[K,N] row-major -> packed B[N,K] hi/lo
__global__ void pack_w_kernel(const float* __restrict__ W,
                              __nv_bfloat16* __restrict__ Ph,
                              __nv_bfloat16* __restrict__ Pl,
                              int K, int N)
{
    long idx = (long)blockIdx.x * blockDim.x + threadIdx.x;
    long total = (long)N * (K >> 3);
    if (idx >= total) return;
    int n  = (int)(idx % N);
    int kg = (int)(idx / N);
    int k  = kg << 3;

    float v[8];
#pragma unroll
    for (int i = 0; i < 8; i++) v[i] = W[(size_t)(k + i) * N + n];

    __align__(16) __nv_bfloat16 hi[8], lo[8];
#pragma unroll
    for (int i = 0; i < 8; i++) {
        hi[i] = __float2bfloat16(v[i]);
        lo[i] = __float2bfloat16(v[i] - __bfloat162float(hi[i]));
    }

    int nt = n >> 7, rn = n & 127, ch = k >> 6, c = k & 63;
    size_t blk = (size_t)nt * (K >> 6) + ch;
    uint32_t sw = sw128((uint32_t)(rn * 128 + c * 2));
    size_t off = blk * 16384 + sw;
    *(uint4*)((char*)Ph + off) = *(const uint4*)hi;
    *(uint4*)((char*)Pl + off) = *(const uint4*)lo;
}

// ---------------------------------------------------------------------------
// mma.sync GEMM: C[M,N] = epi(Asplit @ Bsplit^T + bias), bf16x3 split.
// grid = (N/128, M/128), 256 threads, BK=64, 3-stage cp.async pipeline.
// EPI: 0 none, 1 gelu, 2 sigmoid, 3 sigmoid*5, 4 +resid
// ---------------------------------------------------------------------------
#define NSTAGE 3
#define TENSOR_BYTES 16384
#define STAGE_BYTES  (4 * TENSOR_BYTES)     // Ah, Al, Bh, Bl
#define GEMM_SMEM    (NSTAGE * STAGE_BYTES) // 196608

__device__ __forceinline__ float gelu_exact(float v) {
    return 0.5f * v * (1.0f + erff(v * 0.70710678118654752f));
}

__device__ __forceinline__ void copy_stage(uint32_t sdst,
                                           const char* Ah, const char* Al,
                                           const char* Bh, const char* Bl, int tid)
{
#pragma unroll
    for (int j = 0; j < 4; j++) {
        uint32_t off = (uint32_t)(tid + j * 256) * 16;
        cp16(sdst + off,                    Ah + off);
        cp16(sdst + TENSOR_BYTES + off,     Al + off);
        cp16(sdst + 2 * TENSOR_BYTES + off, Bh + off);
        cp16(sdst + 3 * TENSOR_BYTES + off, Bl + off);
    }
}

template <int EPI>
__global__ __launch_bounds__(256, 1)
void gemm_mma(const __nv_bfloat16* __restrict__ Ahp, const __nv_bfloat16* __restrict__ Alp,
              const __nv_bfloat16* __restrict__ Bhp, const __nv_bfloat16* __restrict__ Blp,
              const float* __restrict__ bias, float* __restrict__ C,
              const float* __restrict__ resid, int N, int K)
{
    extern __shared__ __align__(1024) char dsmem[];
    const uint32_t sbase = smem_u32(dsmem);

    const int tid  = threadIdx.x;
    const int wid  = tid >> 5;
    const int lane = tid & 31;
    const int wm   = wid & 3;       // 0..3 -> m offset wm*32
    const int wn   = wid >> 2;      // 0..1 -> n offset wn*64

    const int nch = K >> 6;
    const char* srcAh = (const char*)(Ahp + (size_t)blockIdx.y * nch * 8192);
    const char* srcAl = (const char*)(Alp + (size_t)blockIdx.y * nch * 8192);
    const char* srcBh = (const char*)(Bhp + (size_t)blockIdx.x * nch * 8192);
    const char* srcBl = (const char*)(Blp + (size_t)blockIdx.x * nch * 8192);

    float acc[2][8][4];
#pragma unroll
    for (int i = 0; i < 2; i++)
#pragma unroll
        for (int j = 0; j < 8; j++)
#pragma unroll
            for (int q = 0; q < 4; q++) acc[i][j][q] = 0.f;

    // prologue: prefetch chunks 0 .. NSTAGE-2
#pragma unroll
    for (int c = 0; c < NSTAGE - 1; c++) {
        if (c < nch) {
            copy_stage(sbase + c * STAGE_BYTES,
                       srcAh + (size_t)c * TENSOR_BYTES, srcAl + (size_t)c * TENSOR_BYTES,
                       srcBh + (size_t)c * TENSOR_BYTES, srcBl + (size_t)c * TENSOR_BYTES, tid);
        }
        CP_COMMIT();
    }

    const int a_row  = lane & 15;          // ldmatrix row within 16
    const int a_kb   = (lane >> 4) * 16;   // 0 or 16 bytes (k half)

    for (int ch = 0; ch < nch; ++ch) {
        CP_WAIT(NSTAGE - 2);
        __syncthreads();

        const int pc = ch + NSTAGE - 1;
        if (pc < nch) {
            copy_stage(sbase + (pc % NSTAGE) * STAGE_BYTES,
                       srcAh + (size_t)pc * TENSOR_BYTES, srcAl + (size_t)pc * TENSOR_BYTES,
                       srcBh + (size_t)pc * TENSOR_BYTES, srcBl + (size_t)pc * TENSOR_BYTES, tid);
        }
        CP_COMMIT();

        const uint32_t sAh = sbase + (ch % NSTAGE) * STAGE_BYTES;
        const uint32_t sAl = sAh + TENSOR_BYTES;
        const uint32_t sBh = sAh + 2 * TENSOR_BYTES;
        const uint32_t sBl = sAh + 3 * TENSOR_BYTES;

#pragma unroll
        for (int k16 = 0; k16 < 4; ++k16) {
            const int kb = k16 * 32 + a_kb;
            uint32_t ah[2][4], al[2][4], bh[4][4], bl[4][4];

#pragma unroll
            for (int im = 0; im < 2; im++) {
                uint32_t b = (uint32_t)((wm * 32 + im * 16 + a_row) * 128 + kb);
                ldsm4(ah[im], sAh + sw128(b));
                ldsm4(al[im], sAl + sw128(b));
            }
#pragma unroll
            for (int jn2 = 0; jn2 < 4; jn2++) {
                uint32_t b = (uint32_t)((wn * 64 + jn2 * 16 + a_row) * 128 + kb);
                ldsm4(bh[jn2], sBh + sw128(b));
                ldsm4(bl[jn2], sBl + sw128(b));
            }

#pragma unroll
            for (int im = 0; im < 2; im++) {
#pragma unroll
                for (int jn = 0; jn < 8; jn++) {
                    const int j2 = jn >> 1, jo = jn & 1;
                    uint32_t bh0 = bh[j2][jo], bh1 = bh[j2][2 + jo];
                    uint32_t bl0 = bl[j2][jo], bl1 = bl[j2][2 + jo];
                    mma16816(acc[im][jn], ah[im], bh0, bh1);  // hi*hi
                    mma16816(acc[im][jn], ah[im], bl0, bl1);  // hi*lo
                    mma16816(acc[im][jn], al[im], bh0, bh1);  // lo*hi
                }
            }
        }
        __syncthreads();
    }

    // ---------------- epilogue ----------------
    const int m0 = blockIdx.y * 128 + wm * 32 + (lane >> 2);
    const int n0 = blockIdx.x * 128 + wn * 64 + (lane & 3) * 2;

#pragma unroll
    for (int im = 0; im < 2; im++) {
#pragma unroll
        for (int half = 0; half < 2; half++) {
            const int row = m0 + im * 16 + half * 8;
            float* crow = C + (size_t)row * N;
            const float* rrow = (EPI == 4) ? (resid + (size_t)row * N) : nullptr;
#pragma unroll
            for (int jn = 0; jn < 8; jn++) {
                const int col = n0 + jn * 8;
                float v0 = acc[im][jn][half * 2 + 0] + bias[col];
                float v1 = acc[im][jn][half * 2 + 1] + bias[col + 1];
                if (EPI == 1) { v0 = gelu_exact(v0); v1 = gelu_exact(v1); }
                else if (EPI == 2) { v0 = 1.f / (1.f + expf(-v0)); v1 = 1.f / (1.f + expf(-v1)); }
                else if (EPI == 3) { v0 = 5.f / (1.f + expf(-v0)); v1 = 5.f / (1.f + expf(-v1)); }
                else if (EPI == 4) { v0 += rrow[col]; v1 += rrow[col + 1]; }
                float2 o = make_float2(v0, v1);
                *(float2*)(crow + col) = o;
            }
        }
    }
}

// ---------------------------------------------------------------------------
// scan kernel: one thread per (b,d) channel
// ---------------------------------------------------------------------------
__global__ void scan_kernel(const float* __restrict__ x,
                            const float* __restrict__ omega,
                            const float* __restrict__ gate,
                            const float* __restrict__ mag,
                            const float* __restrict__ phii,
                            const float* __restrict__ qoff,
                            const float* __restrict__ iscale,
                            float* __restrict__ ctx)
{
    const int b = blockIdx.y;
    const int d = blockIdx.x * 32 + threadIdx.x;
    const float isc = fabsf(iscale[d]);

    size_t base  = ((size_t)b * Sz) * Dz + d;
    size_t cbase = ((size_t)b * Sz) * D4 + d;

    float phic = 0.f, mr = 0.f, mi = 0.f, cm = 0.f;

    size_t idx = base;
    float o  = omega[idx], g = gate[idx], m = mag[idx];
    float xi = x[idx],     pi = phii[idx], qo = qoff[idx];

    for (int s = 0; s < Sz; ++s) {
        float o_n, g_n, m_n, xi_n, pi_n, qo_n;
        if (s + 1 < Sz) {
            size_t idx2 = idx + Dz;
            o_n = omega[idx2]; g_n = gate[idx2]; m_n = mag[idx2];
            xi_n = x[idx2];    pi_n = phii[idx2]; qo_n = qoff[idx2];
        } else {
            o_n = g_n = m_n = xi_n = pi_n = qo_n = 0.f;
        }

        phic += g * o * isc;
        float phi = pi + phic;
        float c, sn;
        sincosf(phi, &sn, &c);
        float wc = m * xi;
        mr += wc * c;
        mi += wc * sn;
        cm += m;
        float r    = 1.0f / sqrtf(cm + 1e-8f);
        float mrn  = mr * r;
        float min_ = mi * r;
        float cq, sq;
        sincosf(phi + qo, &sq, &cq);

        size_t ci = cbase + (size_t)s * D4;
        ctx[ci]          = xi * c;
        ctx[ci + Dz]     = xi * sn;
        ctx[ci + 2 * Dz] = mrn * cq + min_ * sq;
        ctx[ci + 3 * Dz] = min_ * cq - mrn * sq;

        o = o_n; g = g_n; m = m_n; xi = xi_n; pi = pi_n; qo = qo_n;
        idx += Dz;
    }
}

// ---------------------------------------------------------------------------
// layernorm (in-place), dim = 2048
// ---------------------------------------------------------------------------
__device__ __forceinline__ float block_reduce_sum(float val)
{
    __shared__ float sh[8];
    int lane = threadIdx.x & 31, w = threadIdx.x >> 5;
    __syncthreads();
#pragma unroll
    for (int o = 16; o > 0; o >>= 1) val += __shfl_down_sync(0xffffffffu, val, o);
    if (lane == 0) sh[w] = val;
    __syncthreads();
    if (w == 0) {
        val = (lane < 8) ? sh[lane] : 0.f;
#pragma unroll
        for (int o = 4; o > 0; o >>= 1) val += __shfl_down_sync(0xffffffffu, val, o);
        if (lane == 0) sh[0] = val;
    }
    __syncthreads();
    return sh[0];
}

__global__ __launch_bounds__(256)
void ln_kernel(float* __restrict__ ctx, const float* __restrict__ gamma,
               const float* __restrict__ beta)
{
    const int row = blockIdx.x;
    float* p = ctx + (size_t)row * D4;
    const int t = threadIdx.x;

    float v[8];
    float sum = 0.f;
#pragma unroll
    for (int i = 0; i < 8; i++) { v[i] = p[t + 256 * i]; sum += v[i]; }
    sum = block_reduce_sum(sum);
    const float mean = sum * (1.0f / (float)D4);

    float sq = 0.f;
#pragma unroll
    for (int i = 0; i < 8; i++) { float dv = v[i] - mean; sq += dv * dv; }
    sq = block_reduce_sum(sq);
    const float rstd = 1.0f / sqrtf(sq * (1.0f / (float)D4) + 1e-5f);

#pragma unroll
    for (int i = 0; i < 8; i++) {
        const int col = t + 256 * i;
        p[col] = (v[i] - mean) * rstd * gamma[col] + beta[col];
    }
}

// ---------------------------------------------------------------------------
// launch
// ---------------------------------------------------------------------------
static inline void* sym(const void* s) { void* p = nullptr; cudaGetSymbolAddress(&p, s); return p; }

extern "C" void kernel_launch(void* const* d_in, const int* in_sizes, int n_in,
                              void* d_out, int out_size)
{
    const float* x       = (const float*)d_in[0];
    const float* W_omega = (const float*)d_in[1];
    const float* b_omega = (const float*)d_in[2];
    const float* W_p1    = (const float*)d_in[3];
    const float* b_p1    = (const float*)d_in[4];
    const float* W_p2    = (const float*)d_in[5];
    const float* b_p2    = (const float*)d_in[6];
    const float* W_gate  = (const float*)d_in[7];
    const float* b_gate  = (const float*)d_in[8];
    const float* iscale  = (const float*)d_in[9];
    const float* W_mag   = (const float*)d_in[10];
    const float* b_mag   = (const float*)d_in[11];
    const float* W_qoff  = (const float*)d_in[12];
    const float* b_qoff  = (const float*)d_in[13];
    const float* ln_g    = (const float*)d_in[14];
    const float* ln_b    = (const float*)d_in[15];
    const float* W_o1    = (const float*)d_in[16];
    const float* b_o1    = (const float*)d_in[17];
    const float* W_o2    = (const float*)d_in[18];
    const float* b_o2    = (const float*)d_in[19];
    float* out = (float*)d_out;

    float* p_omega = (float*)sym(g_omega);
    float* p_mag   = (float*)sym(g_mag);
    float* p_gate  = (float*)sym(g_gate);
    float* p_qoff  = (float*)sym(g_qoff);
    float* p_p1h   = (float*)sym(g_p1h);
    float* p_phii  = (float*)sym(g_phii);
    float* p_ctx   = (float*)sym(g_ctx);
    float* p_h     = (float*)sym(g_h);

    __nv_bfloat16* xp_h  = (__nv_bfloat16*)sym(g_xp_h);
    __nv_bfloat16* xp_l  = (__nv_bfloat16*)sym(g_xp_l);
    __nv_bfloat16* p1p_h = (__nv_bfloat16*)sym(g_p1p_h);
    __nv_bfloat16* p1p_l = (__nv_bfloat16*)sym(g_p1p_l);
    __nv_bfloat16* cxp_h = (__nv_bfloat16*)sym(g_ctxp_h);
    __nv_bfloat16* cxp_l = (__nv_bfloat16*)sym(g_ctxp_l);
    __nv_bfloat16* hp_h  = (__nv_bfloat16*)sym(g_hp_h);
    __nv_bfloat16* hp_l  = (__nv_bfloat16*)sym(g_hp_l);

    __nv_bfloat16* wom_h = (__nv_bfloat16*)sym(g_wom_h); __nv_bfloat16* wom_l = (__nv_bfloat16*)sym(g_wom_l);
    __nv_bfloat16* wp1_h = (__nv_bfloat16*)sym(g_wp1_h); __nv_bfloat16* wp1_l = (__nv_bfloat16*)sym(g_wp1_l);
    __nv_bfloat16* wp2_h = (__nv_bfloat16*)sym(g_wp2_h); __nv_bfloat16* wp2_l = (__nv_bfloat16*)sym(g_wp2_l);
    __nv_bfloat16* wgt_h = (__nv_bfloat16*)sym(g_wgt_h); __nv_bfloat16* wgt_l = (__nv_bfloat16*)sym(g_wgt_l);
    __nv_bfloat16* wmg_h = (__nv_bfloat16*)sym(g_wmg_h); __nv_bfloat16* wmg_l = (__nv_bfloat16*)sym(g_wmg_l);
    __nv_bfloat16* wqo_h = (__nv_bfloat16*)sym(g_wqo_h); __nv_bfloat16* wqo_l = (__nv_bfloat16*)sym(g_wqo_l);
    __nv_bfloat16* wo1_h = (__nv_bfloat16*)sym(g_wo1_h); __nv_bfloat16* wo1_l = (__nv_bfloat16*)sym(g_wo1_l);
    __nv_bfloat16* wo2_h = (__nv_bfloat16*)sym(g_wo2_h); __nv_bfloat16* wo2_l = (__nv_bfloat16*)sym(g_wo2_l);

    cudaFuncSetAttribute(gemm_mma<0>, cudaFuncAttributeMaxDynamicSharedMemorySize, GEMM_SMEM);
    cudaFuncSetAttribute(gemm_mma<1>, cudaFuncAttributeMaxDynamicSharedMemorySize, GEMM_SMEM);
    cudaFuncSetAttribute(gemm_mma<2>, cudaFuncAttributeMaxDynamicSharedMemorySize, GEMM_SMEM);
    cudaFuncSetAttribute(gemm_mma<3>, cudaFuncAttributeMaxDynamicSharedMemorySize, GEMM_SMEM);
    cudaFuncSetAttribute(gemm_mma<4>, cudaFuncAttributeMaxDynamicSharedMemorySize, GEMM_SMEM);

    // --- pack weights ---
    {
        long t = (long)Dz * (Dz >> 3);
        int blks = (int)((t + 255) / 256);
        pack_w_kernel<<<blks, 256>>>(W_omega, wom_h, wom_l, Dz, Dz);
        pack_w_kernel<<<blks, 256>>>(W_p1,    wp1_h, wp1_l, Dz, Dz);
        pack_w_kernel<<<blks, 256>>>(W_p2,    wp2_h, wp2_l, Dz, Dz);
        pack_w_kernel<<<blks, 256>>>(W_gate,  wgt_h, wgt_l, Dz, Dz);
        pack_w_kernel<<<blks, 256>>>(W_mag,   wmg_h, wmg_l, Dz, Dz);
        pack_w_kernel<<<blks, 256>>>(W_qoff,  wqo_h, wqo_l, Dz, Dz);
        long t1 = (long)D2 * (D4 >> 3);
        pack_w_kernel<<<(int)((t1 + 255) / 256), 256>>>(W_o1, wo1_h, wo1_l, D4, D2);
        long t2 = (long)Dz * (D2 >> 3);
        pack_w_kernel<<<(int)((t2 + 255) / 256), 256>>>(W_o2, wo2_h, wo2_l, D2, Dz);
    }

    // --- pack x ---
    {
        long t = (long)Mz * Dz / 8;
        pack_a_kernel<<<(int)((t + 255) / 256), 256>>>(x, xp_h, xp_l, Dz, t);
    }

    dim3 blk(256);
    dim3 grdD(Dz / 128, Mz / 128);   // (4, 256)
    dim3 grd2(D2 / 128, Mz / 128);   // (8, 256)

    // projections
    gemm_mma<0><<<grdD, blk, GEMM_SMEM>>>(xp_h, xp_l, wom_h, wom_l, b_omega, p_omega, nullptr, Dz, Dz);
    gemm_mma<3><<<grdD, blk, GEMM_SMEM>>>(xp_h, xp_l, wmg_h, wmg_l, b_mag,   p_mag,   nullptr, Dz, Dz);
    gemm_mma<2><<<grdD, blk, GEMM_SMEM>>>(xp_h, xp_l, wgt_h, wgt_l, b_gate,  p_gate,  nullptr, Dz, Dz);
    gemm_mma<0><<<grdD, blk, GEMM_SMEM>>>(xp_h, xp_l, wqo_h, wqo_l, b_qoff,  p_qoff,  nullptr, Dz, Dz);
    gemm_mma<1><<<grdD, blk, GEMM_SMEM>>>(xp_h, xp_l, wp1_h, wp1_l, b_p1,    p_p1h,   nullptr, Dz, Dz);

    // p2 projection
    {
        long t = (long)Mz * Dz / 8;
        pack_a_kernel<<<(int)((t + 255) / 256), 256>>>(p_p1h, p1p_h, p1p_l, Dz, t);
    }
    gemm_mma<0><<<grdD, blk, GEMM_SMEM>>>(p1p_h, p1p_l, wp2_h, wp2_l, b_p2, p_phii, nullptr, Dz, Dz);

    // scan -> ctx [Mz, 2048]
    dim3 sgrid(Dz / 32, Bz);
    scan_kernel<<<sgrid, 32>>>(x, p_omega, p_gate, p_mag, p_phii, p_qoff, iscale, p_ctx);

    // layernorm
    ln_kernel<<<Mz, 256>>>(p_ctx, ln_g, ln_b);

    // output MLP
    {
        long t = (long)Mz * D4 / 8;
        pack_a_kernel<<<(int)((t + 255) / 256), 256>>>(p_ctx, cxp_h, cxp_l, D4, t);
    }
    gemm_mma<1><<<grd2, blk, GEMM_SMEM>>>(cxp_h, cxp_l, wo1_h, wo1_l, b_o1, p_h, nullptr, D2, D4);
    {
        long t = (long)Mz * D2 / 8;
        pack_a_kernel<<<(int)((t + 255) / 256), 256>>>(p_h, hp_h, hp_l, D2, t);
    }
    gemm_mma<4><<<grdD, blk, GEMM_SMEM>>>(hp_h, hp_l, wo2_h, wo2_l, b_o2, out, x, Dz, D2);
}

// round 4
// speedup vs baseline: 3.2227x; 1.8334x over previous
#include <cuda_runtime.h>
#include <cuda_bf16.h>
#include <math.h>
#include <stdint.h>

#define Bz 8
#define Sz 4096
#define Dz 512
#define Mz (Bz * Sz)          // 32768 rows
#define D4 (4 * Dz)           // 2048
#define D2 (2 * Dz)           // 1024

#define SCH 64                // scan chunks
#define SLEN (Sz / SCH)       // 64 steps per chunk
#define NCHAN (Bz * Dz)       // 4096 channels

// ---------------------------------------------------------------------------
// Scratch (static device globals; no allocation)
// ---------------------------------------------------------------------------
__device__ float g_omega[(size_t)Mz * Dz];
__device__ float g_mag  [(size_t)Mz * Dz];
__device__ float g_gate [(size_t)Mz * Dz];
__device__ float g_qoff [(size_t)Mz * Dz];
__device__ float g_phii [(size_t)Mz * Dz];
__device__ float g_ctx  [(size_t)Mz * D4];

// scan chunk statistics [chunk][channel]
__device__ float g_sphi[SCH * NCHAN];
__device__ float g_sm  [SCH * NCHAN];
__device__ float g_smr [SCH * NCHAN];
__device__ float g_smi [SCH * NCHAN];

// packed bf16 hi/lo activations (SW128 tile-blocked layout)
__device__ __nv_bfloat16 g_xp_h [(size_t)Mz * Dz];
__device__ __nv_bfloat16 g_xp_l [(size_t)Mz * Dz];
__device__ __nv_bfloat16 g_p1p_h[(size_t)Mz * Dz];
__device__ __nv_bfloat16 g_p1p_l[(size_t)Mz * Dz];
__device__ __nv_bfloat16 g_ctxp_h[(size_t)Mz * D4];
__device__ __nv_bfloat16 g_ctxp_l[(size_t)Mz * D4];
__device__ __nv_bfloat16 g_hp_h [(size_t)Mz * D2];
__device__ __nv_bfloat16 g_hp_l [(size_t)Mz * D2];

// packed bf16 hi/lo weights (transposed to [N,K], SW128 tile-blocked)
__device__ __nv_bfloat16 g_wom_h[Dz * Dz],  g_wom_l[Dz * Dz];
__device__ __nv_bfloat16 g_wp1_h[Dz * Dz],  g_wp1_l[Dz * Dz];
__device__ __nv_bfloat16 g_wp2_h[Dz * Dz],  g_wp2_l[Dz * Dz];
__device__ __nv_bfloat16 g_wgt_h[Dz * Dz],  g_wgt_l[Dz * Dz];
__device__ __nv_bfloat16 g_wmg_h[Dz * Dz],  g_wmg_l[Dz * Dz];
__device__ __nv_bfloat16 g_wqo_h[Dz * Dz],  g_wqo_l[Dz * Dz];
__device__ __nv_bfloat16 g_wo1_h[(size_t)D4 * D2],  g_wo1_l[(size_t)D4 * D2];
__device__ __nv_bfloat16 g_wo2_h[D2 * Dz],  g_wo2_l[D2 * Dz];

// ---------------------------------------------------------------------------
// PTX helpers (sm_80-compatible subset: cp.async, ldmatrix, mma.sync)
// ---------------------------------------------------------------------------
__device__ __forceinline__ uint32_t smem_u32(const void* p) {
    uint32_t a;
    asm("{ .reg .u64 t; cvta.to.shared.u64 t, %1; cvt.u32.u64 %0, t; }" : "=r"(a) : "l"(p));
    return a;
}

__device__ __forceinline__ void cp16(uint32_t dst, const void* src) {
    asm volatile("cp.async.cg.shared.global [%0], [%1], 16;" :: "r"(dst), "l"(src));
}
#define CP_COMMIT() asm volatile("cp.async.commit_group;" ::: "memory")
#define CP_WAIT(n)  asm volatile("cp.async.wait_group %0;" :: "n"(n) : "memory")

__device__ __forceinline__ void ldsm4(uint32_t* r, uint32_t addr) {
    asm volatile("ldmatrix.sync.aligned.m8n8.x4.shared.b16 {%0,%1,%2,%3}, [%4];"
                 : "=r"(r[0]), "=r"(r[1]), "=r"(r[2]), "=r"(r[3]) : "r"(addr));
}

__device__ __forceinline__ void mma16816(float* d, const uint32_t* a, uint32_t b0, uint32_t b1) {
    asm volatile(
        "mma.sync.aligned.m16n8k16.row.col.f32.bf16.bf16.f32 "
        "{%0,%1,%2,%3}, {%4,%5,%6,%7}, {%8,%9}, {%0,%1,%2,%3};"
        : "+f"(d[0]), "+f"(d[1]), "+f"(d[2]), "+f"(d[3])
        : "r"(a[0]), "r"(a[1]), "r"(a[2]), "r"(a[3]), "r"(b0), "r"(b1));
}

__device__ __forceinline__ uint32_t sw128(uint32_t b) { return b ^ ((b >> 3) & 0x70); }

// ---------------------------------------------------------------------------
// Packing kernels: fp32 -> bf16 hi/lo in SW128 tile-blocked layout.
// ---------------------------------------------------------------------------
__global__ void pack_a_kernel(const float* __restrict__ A,
                              __nv_bfloat16* __restrict__ Ph,
                              __nv_bfloat16* __restrict__ Pl,
                              int K, long total8)
{
    long idx = (long)blockIdx.x * blockDim.x + threadIdx.x;
    if (idx >= total8) return;
    int kk8 = K >> 3;
    int row = (int)(idx / kk8);
    int k   = (int)(idx % kk8) << 3;

    const float4* p = (const float4*)(A + (size_t)row * K + k);
    float4 a = p[0], b = p[1];
    float v[8] = {a.x, a.y, a.z, a.w, b.x, b.y, b.z, b.w};

    __align__(16) __nv_bfloat16 hi[8], lo[8];
#pragma unroll
    for (int i = 0; i < 8; i++) {
        hi[i] = __float2bfloat16(v[i]);
        lo[i] = __float2bfloat16(v[i] - __bfloat162float(hi[i]));
    }

    int mt = row >> 7, r = row & 127, ch = k >> 6, c = k & 63;
    size_t blk = (size_t)mt * (K >> 6) + ch;
    uint32_t sw = sw128((uint32_t)(r * 128 + c * 2));
    size_t off = blk * 16384 + sw;   // bytes
    *(uint4*)((char*)Ph + off) = *(const uint4*)hi;
    *(uint4*)((char*)Pl + off) = *(const uint4*)lo;
}

__global__ void pack_w_kernel(const float* __restrict__ W,
                              __nv_bfloat16* __restrict__ Ph,
                              __nv_bfloat16* __restrict__ Pl,
                              int K, int N)
{
    long idx = (long)blockIdx.x * blockDim.x + threadIdx.x;
    long total = (long)N * (K >> 3);
    if (idx >= total) return;
    int n  = (int)(idx % N);
    int kg = (int)(idx / N);
    int k  = kg << 3;

    float v[8];
#pragma unroll
    for (int i = 0; i < 8; i++) v[i] = W[(size_t)(k + i) * N + n];

    __align__(16) __nv_bfloat16 hi[8], lo[8];
#pragma unroll
    for (int i = 0; i < 8; i++) {
        hi[i] = __float2bfloat16(v[i]);
        lo[i] = __float2bfloat16(v[i] - __bfloat162float(hi[i]));
    }

    int nt = n >> 7, rn = n & 127, ch = k >> 6, c = k & 63;
    size_t blk = (size_t)nt * (K >> 6) + ch;
    uint32_t sw = sw128((uint32_t)(rn * 128 + c * 2));
    size_t off = blk * 16384 + sw;
    *(uint4*)((char*)Ph + off) = *(const uint4*)hi;
    *(uint4*)((char*)Pl + off) = *(const uint4*)lo;
}

// ---------------------------------------------------------------------------
// mma.sync GEMM, bf16x3 split. grid=(N/128, M/128), 256 thr, BK=64, 3 stages.
// EPI: 0 none, 1 gelu, 2 sigmoid, 3 sigmoid*5, 4 +resid
// PACK: write bf16 hi/lo tile-blocked instead of fp32 C
// ---------------------------------------------------------------------------
#define NSTAGE 3
#define TENSOR_BYTES 16384
#define STAGE_BYTES  (4 * TENSOR_BYTES)
#define GEMM_SMEM    (NSTAGE * STAGE_BYTES)

__device__ __forceinline__ float gelu_exact(float v) {
    return 0.5f * v * (1.0f + erff(v * 0.70710678118654752f));
}

__device__ __forceinline__ void copy_stage(uint32_t sdst,
                                           const char* Ah, const char* Al,
                                           const char* Bh, const char* Bl, int tid)
{
#pragma unroll
    for (int j = 0; j < 4; j++) {
        uint32_t off = (uint32_t)(tid + j * 256) * 16;
        cp16(sdst + off,                    Ah + off);
        cp16(sdst + TENSOR_BYTES + off,     Al + off);
        cp16(sdst + 2 * TENSOR_BYTES + off, Bh + off);
        cp16(sdst + 3 * TENSOR_BYTES + off, Bl + off);
    }
}

template <int EPI, int PACK>
__global__ __launch_bounds__(256, 1)
void gemm_mma(const __nv_bfloat16* __restrict__ Ahp, const __nv_bfloat16* __restrict__ Alp,
              const __nv_bfloat16* __restrict__ Bhp, const __nv_bfloat16* __restrict__ Blp,
              const float* __restrict__ bias, float* __restrict__ C,
              __nv_bfloat16* __restrict__ Ph, __nv_bfloat16* __restrict__ Pl,
              const float* __restrict__ resid, int N, int K)
{
    extern __shared__ __align__(1024) char dsmem[];
    const uint32_t sbase = smem_u32(dsmem);

    const int tid  = threadIdx.x;
    const int wid  = tid >> 5;
    const int lane = tid & 31;
    const int wm   = wid & 3;
    const int wn   = wid >> 2;

    const int nch = K >> 6;
    const char* srcAh = (const char*)(Ahp + (size_t)blockIdx.y * nch * 8192);
    const char* srcAl = (const char*)(Alp + (size_t)blockIdx.y * nch * 8192);
    const char* srcBh = (const char*)(Bhp + (size_t)blockIdx.x * nch * 8192);
    const char* srcBl = (const char*)(Blp + (size_t)blockIdx.x * nch * 8192);

    float acc[2][8][4];
#pragma unroll
    for (int i = 0; i < 2; i++)
#pragma unroll
        for (int j = 0; j < 8; j++)
#pragma unroll
            for (int q = 0; q < 4; q++) acc[i][j][q] = 0.f;

#pragma unroll
    for (int c = 0; c < NSTAGE - 1; c++) {
        if (c < nch) {
            copy_stage(sbase + c * STAGE_BYTES,
                       srcAh + (size_t)c * TENSOR_BYTES, srcAl + (size_t)c * TENSOR_BYTES,
                       srcBh + (size_t)c * TENSOR_BYTES, srcBl + (size_t)c * TENSOR_BYTES, tid);
        }
        CP_COMMIT();
    }

    const int a_row = lane & 15;
    const int a_kb  = (lane >> 4) * 16;

    for (int ch = 0; ch < nch; ++ch) {
        CP_WAIT(NSTAGE - 2);
        __syncthreads();

        const int pc = ch + NSTAGE - 1;
        if (pc < nch) {
            copy_stage(sbase + (pc % NSTAGE) * STAGE_BYTES,
                       srcAh + (size_t)pc * TENSOR_BYTES, srcAl + (size_t)pc * TENSOR_BYTES,
                       srcBh + (size_t)pc * TENSOR_BYTES, srcBl + (size_t)pc * TENSOR_BYTES, tid);
        }
        CP_COMMIT();

        const uint32_t sAh = sbase + (ch % NSTAGE) * STAGE_BYTES;
        const uint32_t sAl = sAh + TENSOR_BYTES;
        const uint32_t sBh = sAh + 2 * TENSOR_BYTES;
        const uint32_t sBl = sAh + 3 * TENSOR_BYTES;

#pragma unroll
        for (int k16 = 0; k16 < 4; ++k16) {
            const int kb = k16 * 32 + a_kb;
            uint32_t ah[2][4], al[2][4], bh[4][4], bl[4][4];

#pragma unroll
            for (int im = 0; im < 2; im++) {
                uint32_t b = (uint32_t)((wm * 32 + im * 16 + a_row) * 128 + kb);
                ldsm4(ah[im], sAh + sw128(b));
                ldsm4(al[im], sAl + sw128(b));
            }
#pragma unroll
            for (int jn2 = 0; jn2 < 4; jn2++) {
                uint32_t b = (uint32_t)((wn * 64 + jn2 * 16 + a_row) * 128 + kb);
                ldsm4(bh[jn2], sBh + sw128(b));
                ldsm4(bl[jn2], sBl + sw128(b));
            }

#pragma unroll
            for (int im = 0; im < 2; im++) {
#pragma unroll
                for (int jn = 0; jn < 8; jn++) {
                    const int j2 = jn >> 1, jo = jn & 1;
                    uint32_t bh0 = bh[j2][jo], bh1 = bh[j2][2 + jo];
                    uint32_t bl0 = bl[j2][jo], bl1 = bl[j2][2 + jo];
                    mma16816(acc[im][jn], ah[im], bh0, bh1);
                    mma16816(acc[im][jn], ah[im], bl0, bl1);
                    mma16816(acc[im][jn], al[im], bh0, bh1);
                }
            }
        }
        __syncthreads();
    }

    // ---------------- epilogue ----------------
    const int m0 = blockIdx.y * 128 + wm * 32 + (lane >> 2);
    const int n0 = blockIdx.x * 128 + wn * 64 + (lane & 3) * 2;
    const int nkc = N >> 6;

#pragma unroll
    for (int im = 0; im < 2; im++) {
#pragma unroll
        for (int half = 0; half < 2; half++) {
            const int row = m0 + im * 16 + half * 8;
            float* crow = C + (size_t)row * N;
            const float* rrow = (EPI == 4) ? (resid + (size_t)row * N) : nullptr;
#pragma unroll
            for (int jn = 0; jn < 8; jn++) {
                const int col = n0 + jn * 8;
                float v0 = acc[im][jn][half * 2 + 0] + bias[col];
                float v1 = acc[im][jn][half * 2 + 1] + bias[col + 1];
                if (EPI == 1) { v0 = gelu_exact(v0); v1 = gelu_exact(v1); }
                else if (EPI == 2) { v0 = 1.f / (1.f + expf(-v0)); v1 = 1.f / (1.f + expf(-v1)); }
                else if (EPI == 3) { v0 = 5.f / (1.f + expf(-v0)); v1 = 5.f / (1.f + expf(-v1)); }
                else if (EPI == 4) { v0 += rrow[col]; v1 += rrow[col + 1]; }

                if (PACK) {
                    __nv_bfloat16 h0 = __float2bfloat16(v0);
                    __nv_bfloat16 h1 = __float2bfloat16(v1);
                    __nv_bfloat16 l0 = __float2bfloat16(v0 - __bfloat162float(h0));
                    __nv_bfloat16 l1 = __float2bfloat16(v1 - __bfloat162float(h1));
                    uint32_t hp = ((uint32_t)__bfloat16_as_ushort(h1) << 16) | __bfloat16_as_ushort(h0);
                    uint32_t lp = ((uint32_t)__bfloat16_as_ushort(l1) << 16) | __bfloat16_as_ushort(l0);
                    size_t blk = (size_t)(row >> 7) * nkc + (col >> 6);
                    uint32_t sw = sw128((uint32_t)((row & 127) * 128 + (col & 63) * 2));
                    size_t off = blk * 16384 + sw;
                    *(uint32_t*)((char*)Ph + off) = hp;
                    *(uint32_t*)((char*)Pl + off) = lp;
                } else {
                    *(float2*)(crow + col) = make_float2(v0, v1);
                }
            }
        }
    }
}

// ---------------------------------------------------------------------------
// Parallel scan: S split into SCH chunks of SLEN.
// ---------------------------------------------------------------------------
// K1: per-chunk sums of phi increments and magnitude
__global__ __launch_bounds__(Dz)
void scan_sum1(const float* __restrict__ omega, const float* __restrict__ gate,
               const float* __restrict__ mag, const float* __restrict__ iscale)
{
    const int chunk = blockIdx.x, b = blockIdx.y, d = threadIdx.x;
    const float isc = fabsf(iscale[d]);
    size_t idx = ((size_t)b * Sz + (size_t)chunk * SLEN) * Dz + d;

    float sp = 0.f, sm = 0.f;
#pragma unroll 4
    for (int s = 0; s < SLEN; ++s) {
        sp += gate[idx] * omega[idx] * isc;
        sm += mag[idx];
        idx += Dz;
    }
    int ch = b * Dz + d;
    g_sphi[chunk * NCHAN + ch] = sp;
    g_sm  [chunk * NCHAN + ch] = sm;
}

// K2: exclusive prefix over chunks (phi, m), in place
__global__ void scan_pfx1()
{
    int ch = blockIdx.x * blockDim.x + threadIdx.x;
    if (ch >= NCHAN) return;
    float rp = 0.f, rm = 0.f;
    for (int c = 0; c < SCH; ++c) {
        int i = c * NCHAN + ch;
        float tp = g_sphi[i]; g_sphi[i] = rp; rp += tp;
        float tm = g_sm[i];   g_sm[i]   = rm; rm += tm;
    }
}

// K3: per-chunk mem_r / mem_i sums given phi base
__global__ __launch_bounds__(Dz)
void scan_sum2(const float* __restrict__ x, const float* __restrict__ omega,
               const float* __restrict__ gate, const float* __restrict__ mag,
               const float* __restrict__ phii, const float* __restrict__ iscale)
{
    const int chunk = blockIdx.x, b = blockIdx.y, d = threadIdx.x;
    const float isc = fabsf(iscale[d]);
    const int ch = b * Dz + d;
    const float phib = g_sphi[chunk * NCHAN + ch];

    size_t idx = ((size_t)b * Sz + (size_t)chunk * SLEN) * Dz + d;
    float phic = 0.f, smr = 0.f, smi = 0.f;
#pragma unroll 4
    for (int s = 0; s < SLEN; ++s) {
        phic += gate[idx] * omega[idx] * isc;
        float phi = phii[idx] + phib + phic;
        float c, sn;
        __sincosf(phi, &sn, &c);
        float wc = mag[idx] * x[idx];
        smr += wc * c;
        smi += wc * sn;
        idx += Dz;
    }
    g_smr[chunk * NCHAN + ch] = smr;
    g_smi[chunk * NCHAN + ch] = smi;
}

// K4: exclusive prefix over chunks (mr, mi), in place
__global__ void scan_pfx2()
{
    int ch = blockIdx.x * blockDim.x + threadIdx.x;
    if (ch >= NCHAN) return;
    float rr = 0.f, ri = 0.f;
    for (int c = 0; c < SCH; ++c) {
        int i = c * NCHAN + ch;
        float tr = g_smr[i]; g_smr[i] = rr; rr += tr;
        float ti = g_smi[i]; g_smi[i] = ri; ri += ti;
    }
}

// K5: final pass, writes ctx [M, 4D]
__global__ __launch_bounds__(Dz)
void scan_final(const float* __restrict__ x, const float* __restrict__ omega,
                const float* __restrict__ gate, const float* __restrict__ mag,
                const float* __restrict__ phii, const float* __restrict__ qoff,
                const float* __restrict__ iscale, float* __restrict__ ctx)
{
    const int chunk = blockIdx.x, b = blockIdx.y, d = threadIdx.x;
    const float isc = fabsf(iscale[d]);
    const int ch = b * Dz + d;
    const float phib = g_sphi[chunk * NCHAN + ch];

    size_t idx   = ((size_t)b * Sz + (size_t)chunk * SLEN) * Dz + d;
    size_t cbase = ((size_t)b * Sz + (size_t)chunk * SLEN) * D4 + d;

    float phic = 0.f;
    float mr = g_smr[chunk * NCHAN + ch];
    float mi = g_smi[chunk * NCHAN + ch];
    float cm = g_sm [chunk * NCHAN + ch];

    for (int s = 0; s < SLEN; ++s) {
        float g = gate[idx], o = omega[idx], m = mag[idx];
        float xi = x[idx], pi = phii[idx], qo = qoff[idx];

        phic += g * o * isc;
        float phi = pi + phib + phic;
        float c, sn;
        __sincosf(phi, &sn, &c);
        float wc = m * xi;
        mr += wc * c;
        mi += wc * sn;
        cm += m;
        float r    = rsqrtf(cm + 1e-8f);
        float mrn  = mr * r;
        float min_ = mi * r;
        float cq, sq;
        __sincosf(phi + qo, &sq, &cq);

        size_t ci = cbase + (size_t)s * D4;
        ctx[ci]          = xi * c;
        ctx[ci + Dz]     = xi * sn;
        ctx[ci + 2 * Dz] = mrn * cq + min_ * sq;
        ctx[ci + 3 * Dz] = min_ * cq - mrn * sq;
        idx += Dz;
    }
}

// ---------------------------------------------------------------------------
// layernorm: read fp32 ctx, write packed bf16 hi/lo only
// ---------------------------------------------------------------------------
__device__ __forceinline__ float block_reduce_sum(float val)
{
    __shared__ float sh[8];
    int lane = threadIdx.x & 31, w = threadIdx.x >> 5;
    __syncthreads();
#pragma unroll
    for (int o = 16; o > 0; o >>= 1) val += __shfl_down_sync(0xffffffffu, val, o);
    if (lane == 0) sh[w] = val;
    __syncthreads();
    if (w == 0) {
        val = (lane < 8) ? sh[lane] : 0.f;
#pragma unroll
        for (int o = 4; o > 0; o >>= 1) val += __shfl_down_sync(0xffffffffu, val, o);
        if (lane == 0) sh[0] = val;
    }
    __syncthreads();
    return sh[0];
}

__global__ __launch_bounds__(256)
void ln_pack_kernel(const float* __restrict__ ctx, const float* __restrict__ gamma,
                    const float* __restrict__ beta,
                    __nv_bfloat16* __restrict__ Ph, __nv_bfloat16* __restrict__ Pl)
{
    const int row = blockIdx.x;
    const float* p = ctx + (size_t)row * D4;
    const int t = threadIdx.x;

    float v[8];
    float sum = 0.f;
#pragma unroll
    for (int i = 0; i < 4; i++) {
        float2 u = *(const float2*)(p + i * 512 + 2 * t);
        v[2 * i] = u.x; v[2 * i + 1] = u.y;
        sum += u.x + u.y;
    }
    sum = block_reduce_sum(sum);
    const float mean = sum * (1.0f / (float)D4);

    float sq = 0.f;
#pragma unroll
    for (int i = 0; i < 8; i++) { float dv = v[i] - mean; sq += dv * dv; }
    sq = block_reduce_sum(sq);
    const float rstd = 1.0f / sqrtf(sq * (1.0f / (float)D4) + 1e-5f);

    const int nkc = D4 >> 6;   // 32 chunks
    const size_t blkrow = (size_t)(row >> 7) * nkc;
    const uint32_t rsw = (uint32_t)((row & 127) * 128);

#pragma unroll
    for (int i = 0; i < 4; i++) {
        const int col = i * 512 + 2 * t;
        float2 gg = *(const float2*)(gamma + col);
        float2 bb = *(const float2*)(beta + col);
        float y0 = (v[2 * i]     - mean) * rstd * gg.x + bb.x;
        float y1 = (v[2 * i + 1] - mean) * rstd * gg.y + bb.y;
        __nv_bfloat16 h0 = __float2bfloat16(y0);
        __nv_bfloat16 h1 = __float2bfloat16(y1);
        __nv_bfloat16 l0 = __float2bfloat16(y0 - __bfloat162float(h0));
        __nv_bfloat16 l1 = __float2bfloat16(y1 - __bfloat162float(h1));
        uint32_t hp = ((uint32_t)__bfloat16_as_ushort(h1) << 16) | __bfloat16_as_ushort(h0);
        uint32_t lp = ((uint32_t)__bfloat16_as_ushort(l1) << 16) | __bfloat16_as_ushort(l0);
        size_t blk = blkrow + (col >> 6);
        uint32_t sw = sw128(rsw + (uint32_t)((col & 63) * 2));
        size_t off = blk * 16384 + sw;
        *(uint32_t*)((char*)Ph + off) = hp;
        *(uint32_t*)((char*)Pl + off) = lp;
    }
}

// ---------------------------------------------------------------------------
// launch
// ---------------------------------------------------------------------------
static inline void* sym(const void* s) { void* p = nullptr; cudaGetSymbolAddress(&p, s); return p; }

extern "C" void kernel_launch(void* const* d_in, const int* in_sizes, int n_in,
                              void* d_out, int out_size)
{
    const float* x       = (const float*)d_in[0];
    const float* W_omega = (const float*)d_in[1];
    const float* b_omega = (const float*)d_in[2];
    const float* W_p1    = (const float*)d_in[3];
    const float* b_p1    = (const float*)d_in[4];
    const float* W_p2    = (const float*)d_in[5];
    const float* b_p2    = (const float*)d_in[6];
    const float* W_gate  = (const float*)d_in[7];
    const float* b_gate  = (const float*)d_in[8];
    const float* iscale  = (const float*)d_in[9];
    const float* W_mag   = (const float*)d_in[10];
    const float* b_mag   = (const float*)d_in[11];
    const float* W_qoff  = (const float*)d_in[12];
    const float* b_qoff  = (const float*)d_in[13];
    const float* ln_g    = (const float*)d_in[14];
    const float* ln_b    = (const float*)d_in[15];
    const float* W_o1    = (const float*)d_in[16];
    const float* b_o1    = (const float*)d_in[17];
    const float* W_o2    = (const float*)d_in[18];
    const float* b_o2    = (const float*)d_in[19];
    float* out = (float*)d_out;

    float* p_omega = (float*)sym(g_omega);
    float* p_mag   = (float*)sym(g_mag);
    float* p_gate  = (float*)sym(g_gate);
    float* p_qoff  = (float*)sym(g_qoff);
    float* p_phii  = (float*)sym(g_phii);
    float* p_ctx   = (float*)sym(g_ctx);

    __nv_bfloat16* xp_h  = (__nv_bfloat16*)sym(g_xp_h);
    __nv_bfloat16* xp_l  = (__nv_bfloat16*)sym(g_xp_l);
    __nv_bfloat16* p1p_h = (__nv_bfloat16*)sym(g_p1p_h);
    __nv_bfloat16* p1p_l = (__nv_bfloat16*)sym(g_p1p_l);
    __nv_bfloat16* cxp_h = (__nv_bfloat16*)sym(g_ctxp_h);
    __nv_bfloat16* cxp_l = (__nv_bfloat16*)sym(g_ctxp_l);
    __nv_bfloat16* hp_h  = (__nv_bfloat16*)sym(g_hp_h);
    __nv_bfloat16* hp_l  = (__nv_bfloat16*)sym(g_hp_l);

    __nv_bfloat16* wom_h = (__nv_bfloat16*)sym(g_wom_h); __nv_bfloat16* wom_l = (__nv_bfloat16*)sym(g_wom_l);
    __nv_bfloat16* wp1_h = (__nv_bfloat16*)sym(g_wp1_h); __nv_bfloat16* wp1_l = (__nv_bfloat16*)sym(g_wp1_l);
    __nv_bfloat16* wp2_h = (__nv_bfloat16*)sym(g_wp2_h); __nv_bfloat16* wp2_l = (__nv_bfloat16*)sym(g_wp2_l);
    __nv_bfloat16* wgt_h = (__nv_bfloat16*)sym(g_wgt_h); __nv_bfloat16* wgt_l = (__nv_bfloat16*)sym(g_wgt_l);
    __nv_bfloat16* wmg_h = (__nv_bfloat16*)sym(g_wmg_h); __nv_bfloat16* wmg_l = (__nv_bfloat16*)sym(g_wmg_l);
    __nv_bfloat16* wqo_h = (__nv_bfloat16*)sym(g_wqo_h); __nv_bfloat16* wqo_l = (__nv_bfloat16*)sym(g_wqo_l);
    __nv_bfloat16* wo1_h = (__nv_bfloat16*)sym(g_wo1_h); __nv_bfloat16* wo1_l = (__nv_bfloat16*)sym(g_wo1_l);
    __nv_bfloat16* wo2_h = (__nv_bfloat16*)sym(g_wo2_h); __nv_bfloat16* wo2_l = (__nv_bfloat16*)sym(g_wo2_l);

    cudaFuncSetAttribute(gemm_mma<0,0>, cudaFuncAttributeMaxDynamicSharedMemorySize, GEMM_SMEM);
    cudaFuncSetAttribute(gemm_mma<1,1>, cudaFuncAttributeMaxDynamicSharedMemorySize, GEMM_SMEM);
    cudaFuncSetAttribute(gemm_mma<2,0>, cudaFuncAttributeMaxDynamicSharedMemorySize, GEMM_SMEM);
    cudaFuncSetAttribute(gemm_mma<3,0>, cudaFuncAttributeMaxDynamicSharedMemorySize, GEMM_SMEM);
    cudaFuncSetAttribute(gemm_mma<4,0>, cudaFuncAttributeMaxDynamicSharedMemorySize, GEMM_SMEM);

    // --- pack weights ---
    {
        long t = (long)Dz * (Dz >> 3);
        int blks = (int)((t + 255) / 256);
        pack_w_kernel<<<blks, 256>>>(W_omega, wom_h, wom_l, Dz, Dz);
        pack_w_kernel<<<blks, 256>>>(W_p1,    wp1_h, wp1_l, Dz, Dz);
        pack_w_kernel<<<blks, 256>>>(W_p2,    wp2_h, wp2_l, Dz, Dz);
        pack_w_kernel<<<blks, 256>>>(W_gate,  wgt_h, wgt_l, Dz, Dz);
        pack_w_kernel<<<blks, 256>>>(W_mag,   wmg_h, wmg_l, Dz, Dz);
        pack_w_kernel<<<blks, 256>>>(W_qoff,  wqo_h, wqo_l, Dz, Dz);
        long t1 = (long)D2 * (D4 >> 3);
        pack_w_kernel<<<(int)((t1 + 255) / 256), 256>>>(W_o1, wo1_h, wo1_l, D4, D2);
        long t2 = (long)Dz * (D2 >> 3);
        pack_w_kernel<<<(int)((t2 + 255) / 256), 256>>>(W_o2, wo2_h, wo2_l, D2, Dz);
    }

    // --- pack x ---
    {
        long t = (long)Mz * Dz / 8;
        pack_a_kernel<<<(int)((t + 255) / 256), 256>>>(x, xp_h, xp_l, Dz, t);
    }

    dim3 blk(256);
    dim3 grdD(Dz / 128, Mz / 128);   // (4, 256)
    dim3 grd2(D2 / 128, Mz / 128);   // (8, 256)

    // projections
    gemm_mma<0,0><<<grdD, blk, GEMM_SMEM>>>(xp_h, xp_l, wom_h, wom_l, b_omega, p_omega, nullptr, nullptr, nullptr, Dz, Dz);
    gemm_mma<3,0><<<grdD, blk, GEMM_SMEM>>>(xp_h, xp_l, wmg_h, wmg_l, b_mag,   p_mag,   nullptr, nullptr, nullptr, Dz, Dz);
    gemm_mma<2,0><<<grdD, blk, GEMM_SMEM>>>(xp_h, xp_l, wgt_h, wgt_l, b_gate,  p_gate,  nullptr, nullptr, nullptr, Dz, Dz);
    gemm_mma<0,0><<<grdD, blk, GEMM_SMEM>>>(xp_h, xp_l, wqo_h, wqo_l, b_qoff,  p_qoff,  nullptr, nullptr, nullptr, Dz, Dz);
    gemm_mma<1,1><<<grdD, blk, GEMM_SMEM>>>(xp_h, xp_l, wp1_h, wp1_l, b_p1,    nullptr, p1p_h,   p1p_l,   nullptr, Dz, Dz);
    gemm_mma<0,0><<<grdD, blk, GEMM_SMEM>>>(p1p_h, p1p_l, wp2_h, wp2_l, b_p2,  p_phii,  nullptr, nullptr, nullptr, Dz, Dz);

    // parallel scan -> ctx [Mz, 2048]
    dim3 sgrid(SCH, Bz);
    scan_sum1<<<sgrid, Dz>>>(p_omega, p_gate, p_mag, iscale);
    scan_pfx1<<<NCHAN / 256, 256>>>();
    scan_sum2<<<sgrid, Dz>>>(x, p_omega, p_gate, p_mag, p_phii, iscale);
    scan_pfx2<<<NCHAN / 256, 256>>>();
    scan_final<<<sgrid, Dz>>>(x, p_omega, p_gate, p_mag, p_phii, p_qoff, iscale, p_ctx);

    // layernorm + pack
    ln_pack_kernel<<<Mz, 256>>>(p_ctx, ln_g, ln_b, cxp_h, cxp_l);

    // output MLP
    gemm_mma<1,1><<<grd2, blk, GEMM_SMEM>>>(cxp_h, cxp_l, wo1_h, wo1_l, b_o1, nullptr, hp_h, hp_l, nullptr, D2, D4);
    gemm_mma<4,0><<<grdD, blk, GEMM_SMEM>>>(hp_h, hp_l, wo2_h, wo2_l, b_o2, out, nullptr, nullptr, x, Dz, D2);
}

// round 5
// speedup vs baseline: 3.3146x; 1.0285x over previous
#include <cuda_runtime.h>
#include <cuda_bf16.h>
#include <math.h>
#include <stdint.h>

#define Bz 8
#define Sz 4096
#define Dz 512
#define Mz (Bz * Sz)          // 32768 rows
#define D4 (4 * Dz)           // 2048
#define D2 (2 * Dz)           // 1024

#define SCH 64                // scan chunks
#define SLEN (Sz / SCH)       // 64 steps per chunk
#define NCHAN (Bz * Dz)       // 4096 channels

// ---------------------------------------------------------------------------
// Scratch (static device globals; no allocation)
// ---------------------------------------------------------------------------
__device__ float g_omega[(size_t)Mz * Dz];
__device__ float g_mag  [(size_t)Mz * Dz];
__device__ float g_gate [(size_t)Mz * Dz];
__device__ float g_qoff [(size_t)Mz * Dz];
__device__ float g_phii [(size_t)Mz * Dz];

// scan chunk statistics [chunk][channel]
__device__ float g_sphi[SCH * NCHAN];
__device__ float g_sm  [SCH * NCHAN];
__device__ float g_smr [SCH * NCHAN];
__device__ float g_smi [SCH * NCHAN];

// packed bf16 hi/lo activations (SW128 tile-blocked layout)
__device__ __nv_bfloat16 g_xp_h [(size_t)Mz * Dz];
__device__ __nv_bfloat16 g_xp_l [(size_t)Mz * Dz];
__device__ __nv_bfloat16 g_p1p_h[(size_t)Mz * Dz];
__device__ __nv_bfloat16 g_p1p_l[(size_t)Mz * Dz];
__device__ __nv_bfloat16 g_ctxp_h[(size_t)Mz * D4];
__device__ __nv_bfloat16 g_ctxp_l[(size_t)Mz * D4];
__device__ __nv_bfloat16 g_hp_h [(size_t)Mz * D2];
__device__ __nv_bfloat16 g_hp_l [(size_t)Mz * D2];

// packed bf16 hi/lo weights (transposed to [N,K], SW128 tile-blocked)
__device__ __nv_bfloat16 g_wom_h[Dz * Dz],  g_wom_l[Dz * Dz];
__device__ __nv_bfloat16 g_wp1_h[Dz * Dz],  g_wp1_l[Dz * Dz];
__device__ __nv_bfloat16 g_wp2_h[Dz * Dz],  g_wp2_l[Dz * Dz];
__device__ __nv_bfloat16 g_wgt_h[Dz * Dz],  g_wgt_l[Dz * Dz];
__device__ __nv_bfloat16 g_wmg_h[Dz * Dz],  g_wmg_l[Dz * Dz];
__device__ __nv_bfloat16 g_wqo_h[Dz * Dz],  g_wqo_l[Dz * Dz];
__device__ __nv_bfloat16 g_wo1_h[(size_t)D4 * D2],  g_wo1_l[(size_t)D4 * D2];
__device__ __nv_bfloat16 g_wo2_h[D2 * Dz],  g_wo2_l[D2 * Dz];

// ---------------------------------------------------------------------------
// PTX helpers (sm_80-compatible subset: cp.async, ldmatrix, mma.sync)
// ---------------------------------------------------------------------------
__device__ __forceinline__ uint32_t smem_u32(const void* p) {
    uint32_t a;
    asm("{ .reg .u64 t; cvta.to.shared.u64 t, %1; cvt.u32.u64 %0, t; }" : "=r"(a) : "l"(p));
    return a;
}

__device__ __forceinline__ void cp16(uint32_t dst, const void* src) {
    asm volatile("cp.async.cg.shared.global [%0], [%1], 16;" :: "r"(dst), "l"(src));
}
#define CP_COMMIT() asm volatile("cp.async.commit_group;" ::: "memory")
#define CP_WAIT(n)  asm volatile("cp.async.wait_group %0;" :: "n"(n) : "memory")

__device__ __forceinline__ void ldsm4(uint32_t* r, uint32_t addr) {
    asm volatile("ldmatrix.sync.aligned.m8n8.x4.shared.b16 {%0,%1,%2,%3}, [%4];"
                 : "=r"(r[0]), "=r"(r[1]), "=r"(r[2]), "=r"(r[3]) : "r"(addr));
}

__device__ __forceinline__ void mma16816(float* d, const uint32_t* a, uint32_t b0, uint32_t b1) {
    asm volatile(
        "mma.sync.aligned.m16n8k16.row.col.f32.bf16.bf16.f32 "
        "{%0,%1,%2,%3}, {%4,%5,%6,%7}, {%8,%9}, {%0,%1,%2,%3};"
        : "+f"(d[0]), "+f"(d[1]), "+f"(d[2]), "+f"(d[3])
        : "r"(a[0]), "r"(a[1]), "r"(a[2]), "r"(a[3]), "r"(b0), "r"(b1));
}

__device__ __forceinline__ uint32_t sw128(uint32_t b) { return b ^ ((b >> 3) & 0x70); }

// ---------------------------------------------------------------------------
// Packing kernels: fp32 -> bf16 hi/lo in SW128 tile-blocked layout.
// ---------------------------------------------------------------------------
__global__ void pack_a_kernel(const float* __restrict__ A,
                              __nv_bfloat16* __restrict__ Ph,
                              __nv_bfloat16* __restrict__ Pl,
                              int K, long total8)
{
    long idx = (long)blockIdx.x * blockDim.x + threadIdx.x;
    if (idx >= total8) return;
    int kk8 = K >> 3;
    int row = (int)(idx / kk8);
    int k   = (int)(idx % kk8) << 3;

    const float4* p = (const float4*)(A + (size_t)row * K + k);
    float4 a = p[0], b = p[1];
    float v[8] = {a.x, a.y, a.z, a.w, b.x, b.y, b.z, b.w};

    __align__(16) __nv_bfloat16 hi[8], lo[8];
#pragma unroll
    for (int i = 0; i < 8; i++) {
        hi[i] = __float2bfloat16(v[i]);
        lo[i] = __float2bfloat16(v[i] - __bfloat162float(hi[i]));
    }

    int mt = row >> 7, r = row & 127, ch = k >> 6, c = k & 63;
    size_t blk = (size_t)mt * (K >> 6) + ch;
    uint32_t sw = sw128((uint32_t)(r * 128 + c * 2));
    size_t off = blk * 16384 + sw;   // bytes
    *(uint4*)((char*)Ph + off) = *(const uint4*)hi;
    *(uint4*)((char*)Pl + off) = *(const uint4*)lo;
}

__global__ void pack_w_kernel(const float* __restrict__ W,
                              __nv_bfloat16* __restrict__ Ph,
                              __nv_bfloat16* __restrict__ Pl,
                              int K, int N)
{
    long idx = (long)blockIdx.x * blockDim.x + threadIdx.x;
    long total = (long)N * (K >> 3);
    if (idx >= total) return;
    int n  = (int)(idx % N);
    int kg = (int)(idx / N);
    int k  = kg << 3;

    float v[8];
#pragma unroll
    for (int i = 0; i < 8; i++) v[i] = W[(size_t)(k + i) * N + n];

    __align__(16) __nv_bfloat16 hi[8], lo[8];
#pragma unroll
    for (int i = 0; i < 8; i++) {
        hi[i] = __float2bfloat16(v[i]);
        lo[i] = __float2bfloat16(v[i] - __bfloat162float(hi[i]));
    }

    int nt = n >> 7, rn = n & 127, ch = k >> 6, c = k & 63;
    size_t blk = (size_t)nt * (K >> 6) + ch;
    uint32_t sw = sw128((uint32_t)(rn * 128 + c * 2));
    size_t off = blk * 16384 + sw;
    *(uint4*)((char*)Ph + off) = *(const uint4*)hi;
    *(uint4*)((char*)Pl + off) = *(const uint4*)lo;
}

// ---------------------------------------------------------------------------
// mma.sync GEMM, bf16x3 split. BM=128, BN=256, BK=64. 256 threads, 2 stages.
// warp grid 2(M) x 4(N); warp tile 64x64.
// EPI: 0 none, 1 gelu, 2 sigmoid, 3 sigmoid*5, 4 +resid
// PACK: write bf16 hi/lo tile-blocked instead of fp32 C
// ---------------------------------------------------------------------------
#define TB 16384                     // bytes per 128x64 tensor tile
#define STAGE_BYTES (6 * TB)         // Ah, Al, Bh(x2), Bl(x2) = 96KB
#define GEMM_SMEM   (2 * STAGE_BYTES)

__device__ __forceinline__ float gelu_exact(float v) {
    return 0.5f * v * (1.0f + erff(v * 0.70710678118654752f));
}

__device__ __forceinline__ void copy_stage2(uint32_t sdst,
                                            const char* Ah, const char* Al,
                                            const char* Bh0, const char* Bh1,
                                            const char* Bl0, const char* Bl1, int tid)
{
#pragma unroll
    for (int j = 0; j < 4; j++) {
        uint32_t o = (uint32_t)tid * 16 + j * 4096;
        cp16(sdst + o,          Ah  + o);
        cp16(sdst + TB + o,     Al  + o);
        cp16(sdst + 2 * TB + o, Bh0 + o);
        cp16(sdst + 3 * TB + o, Bh1 + o);
        cp16(sdst + 4 * TB + o, Bl0 + o);
        cp16(sdst + 5 * TB + o, Bl1 + o);
    }
}

template <int EPI, int PACK>
__global__ __launch_bounds__(256, 1)
void gemm_mma(const __nv_bfloat16* __restrict__ Ahp, const __nv_bfloat16* __restrict__ Alp,
              const __nv_bfloat16* __restrict__ Bhp, const __nv_bfloat16* __restrict__ Blp,
              const float* __restrict__ bias, float* __restrict__ C,
              __nv_bfloat16* __restrict__ Ph, __nv_bfloat16* __restrict__ Pl,
              const float* __restrict__ resid, int N, int K)
{
    extern __shared__ __align__(1024) char dsmem[];
    const uint32_t sbase = smem_u32(dsmem);

    const int tid  = threadIdx.x;
    const int wid  = tid >> 5;
    const int lane = tid & 31;
    const int wn   = wid & 3;       // 0..3  -> n offset wn*64
    const int wm   = wid >> 2;      // 0..1  -> m offset wm*64

    const int nch = K >> 6;
    const char* srcAh = (const char*)Ahp + (size_t)blockIdx.y * nch * TB;
    const char* srcAl = (const char*)Alp + (size_t)blockIdx.y * nch * TB;
    const int nt0 = blockIdx.x * 2;
    const char* srcBh0 = (const char*)Bhp + (size_t)nt0 * nch * TB;
    const char* srcBh1 = srcBh0 + (size_t)nch * TB;
    const char* srcBl0 = (const char*)Blp + (size_t)nt0 * nch * TB;
    const char* srcBl1 = srcBl0 + (size_t)nch * TB;

    float acc[4][8][4];
#pragma unroll
    for (int i = 0; i < 4; i++)
#pragma unroll
        for (int j = 0; j < 8; j++)
#pragma unroll
            for (int q = 0; q < 4; q++) acc[i][j][q] = 0.f;

    // prologue: stage 0 <- chunk 0
    copy_stage2(sbase, srcAh, srcAl, srcBh0, srcBh1, srcBl0, srcBl1, tid);
    CP_COMMIT();

    const int a_row = lane & 15;
    const int a_kb  = (lane >> 4) * 16;

    for (int ch = 0; ch < nch; ++ch) {
        if (ch + 1 < nch) {
            size_t o = (size_t)(ch + 1) * TB;
            copy_stage2(sbase + ((ch + 1) & 1) * STAGE_BYTES,
                        srcAh + o, srcAl + o, srcBh0 + o, srcBh1 + o,
                        srcBl0 + o, srcBl1 + o, tid);
            CP_COMMIT();
            CP_WAIT(1);
        } else {
            CP_WAIT(0);
        }
        __syncthreads();

        const uint32_t sAh = sbase + (ch & 1) * STAGE_BYTES;
        const uint32_t sAl = sAh + TB;
        const uint32_t sBh = sAh + 2 * TB;
        const uint32_t sBl = sAh + 4 * TB;

#pragma unroll
        for (int k16 = 0; k16 < 4; ++k16) {
            const int kb = k16 * 32 + a_kb;
            uint32_t ah[4][4], al[4][4];
#pragma unroll
            for (int im = 0; im < 4; im++) {
                uint32_t b = (uint32_t)((wm * 64 + im * 16 + a_row) * 128 + kb);
                ldsm4(ah[im], sAh + sw128(b));
                ldsm4(al[im], sAl + sw128(b));
            }
#pragma unroll
            for (int j2 = 0; j2 < 4; j2++) {
                uint32_t bh[4], bl[4];
                uint32_t b = (uint32_t)((wn * 64 + j2 * 16 + a_row) * 128 + kb);
                ldsm4(bh, sBh + sw128(b));
                ldsm4(bl, sBl + sw128(b));
#pragma unroll
                for (int im = 0; im < 4; im++) {
#pragma unroll
                    for (int jo = 0; jo < 2; jo++) {
                        const int jn = j2 * 2 + jo;
                        mma16816(acc[im][jn], ah[im], bh[jo], bh[2 + jo]);
                        mma16816(acc[im][jn], ah[im], bl[jo], bl[2 + jo]);
                        mma16816(acc[im][jn], al[im], bh[jo], bh[2 + jo]);
                    }
                }
            }
        }
        __syncthreads();
    }

    // ---------------- epilogue ----------------
    const int m0 = blockIdx.y * 128 + wm * 64 + (lane >> 2);
    const int n0 = blockIdx.x * 256 + wn * 64 + (lane & 3) * 2;
    const int nkc = N >> 6;

#pragma unroll
    for (int im = 0; im < 4; im++) {
#pragma unroll
        for (int half = 0; half < 2; half++) {
            const int row = m0 + im * 16 + half * 8;
            float* crow = C + (size_t)row * N;
            const float* rrow = (EPI == 4) ? (resid + (size_t)row * N) : nullptr;
#pragma unroll
            for (int jn = 0; jn < 8; jn++) {
                const int col = n0 + jn * 8;
                float v0 = acc[im][jn][half * 2 + 0] + bias[col];
                float v1 = acc[im][jn][half * 2 + 1] + bias[col + 1];
                if (EPI == 1) { v0 = gelu_exact(v0); v1 = gelu_exact(v1); }
                else if (EPI == 2) { v0 = 1.f / (1.f + expf(-v0)); v1 = 1.f / (1.f + expf(-v1)); }
                else if (EPI == 3) { v0 = 5.f / (1.f + expf(-v0)); v1 = 5.f / (1.f + expf(-v1)); }
                else if (EPI == 4) { v0 += rrow[col]; v1 += rrow[col + 1]; }

                if (PACK) {
                    __nv_bfloat16 h0 = __float2bfloat16(v0);
                    __nv_bfloat16 h1 = __float2bfloat16(v1);
                    __nv_bfloat16 l0 = __float2bfloat16(v0 - __bfloat162float(h0));
                    __nv_bfloat16 l1 = __float2bfloat16(v1 - __bfloat162float(h1));
                    uint32_t hp = ((uint32_t)__bfloat16_as_ushort(h1) << 16) | __bfloat16_as_ushort(h0);
                    uint32_t lp = ((uint32_t)__bfloat16_as_ushort(l1) << 16) | __bfloat16_as_ushort(l0);
                    size_t blk = (size_t)(row >> 7) * nkc + (col >> 6);
                    uint32_t sw = sw128((uint32_t)((row & 127) * 128 + (col & 63) * 2));
                    size_t off = blk * 16384 + sw;
                    *(uint32_t*)((char*)Ph + off) = hp;
                    *(uint32_t*)((char*)Pl + off) = lp;
                } else {
                    *(float2*)(crow + col) = make_float2(v0, v1);
                }
            }
        }
    }
}

// ---------------------------------------------------------------------------
// Parallel scan: S split into SCH chunks of SLEN. 256 threads, 2 channels each.
// ---------------------------------------------------------------------------
__global__ __launch_bounds__(256)
void scan_sum1(const float* __restrict__ omega, const float* __restrict__ gate,
               const float* __restrict__ mag, const float* __restrict__ iscale)
{
    const int chunk = blockIdx.x, b = blockIdx.y;
    const int d0 = threadIdx.x * 2;
    float2 is2 = *(const float2*)(iscale + d0);
    const float i0 = fabsf(is2.x), i1 = fabsf(is2.y);

    size_t idx = ((size_t)b * Sz + (size_t)chunk * SLEN) * Dz + d0;
    float sp0 = 0.f, sp1 = 0.f, sm0 = 0.f, sm1 = 0.f;
#pragma unroll 4
    for (int s = 0; s < SLEN; ++s) {
        float2 g = *(const float2*)(gate + idx);
        float2 o = *(const float2*)(omega + idx);
        float2 m = *(const float2*)(mag + idx);
        sp0 += g.x * o.x * i0;  sp1 += g.y * o.y * i1;
        sm0 += m.x;             sm1 += m.y;
        idx += Dz;
    }
    int ch = b * Dz + d0;
    *(float2*)&g_sphi[chunk * NCHAN + ch] = make_float2(sp0, sp1);
    *(float2*)&g_sm  [chunk * NCHAN + ch] = make_float2(sm0, sm1);
}

__global__ void scan_pfx1()
{
    int ch = blockIdx.x * blockDim.x + threadIdx.x;
    if (ch >= NCHAN) return;
    float rp = 0.f, rm = 0.f;
    for (int c = 0; c < SCH; ++c) {
        int i = c * NCHAN + ch;
        float tp = g_sphi[i]; g_sphi[i] = rp; rp += tp;
        float tm = g_sm[i];   g_sm[i]   = rm; rm += tm;
    }
}

__global__ __launch_bounds__(256)
void scan_sum2(const float* __restrict__ x, const float* __restrict__ omega,
               const float* __restrict__ gate, const float* __restrict__ mag,
               const float* __restrict__ phii, const float* __restrict__ iscale)
{
    const int chunk = blockIdx.x, b = blockIdx.y;
    const int d0 = threadIdx.x * 2;
    float2 is2 = *(const float2*)(iscale + d0);
    const float i0 = fabsf(is2.x), i1 = fabsf(is2.y);
    const int ch = b * Dz + d0;
    float2 phib = *(const float2*)&g_sphi[chunk * NCHAN + ch];

    size_t idx = ((size_t)b * Sz + (size_t)chunk * SLEN) * Dz + d0;
    float pc0 = 0.f, pc1 = 0.f, r0 = 0.f, r1 = 0.f, q0 = 0.f, q1 = 0.f;
#pragma unroll 4
    for (int s = 0; s < SLEN; ++s) {
        float2 g = *(const float2*)(gate + idx);
        float2 o = *(const float2*)(omega + idx);
        float2 m = *(const float2*)(mag + idx);
        float2 xv = *(const float2*)(x + idx);
        float2 pv = *(const float2*)(phii + idx);
        pc0 += g.x * o.x * i0;
        pc1 += g.y * o.y * i1;
        float c, sn;
        __sincosf(pv.x + phib.x + pc0, &sn, &c);
        float wc = m.x * xv.x;
        r0 += wc * c;  q0 += wc * sn;
        __sincosf(pv.y + phib.y + pc1, &sn, &c);
        wc = m.y * xv.y;
        r1 += wc * c;  q1 += wc * sn;
        idx += Dz;
    }
    *(float2*)&g_smr[chunk * NCHAN + ch] = make_float2(r0, r1);
    *(float2*)&g_smi[chunk * NCHAN + ch] = make_float2(q0, q1);
}

__global__ void scan_pfx2()
{
    int ch = blockIdx.x * blockDim.x + threadIdx.x;
    if (ch >= NCHAN) return;
    float rr = 0.f, ri = 0.f;
    for (int c = 0; c < SCH; ++c) {
        int i = c * NCHAN + ch;
        float tr = g_smr[i]; g_smr[i] = rr; rr += tr;
        float ti = g_smi[i]; g_smi[i] = ri; ri += ti;
    }
}

// ---------------------------------------------------------------------------
// scan_final fused with LayerNorm + bf16 hi/lo packing.
// Block (chunk, b), 256 threads, each owns channels d0=2t, 2t+1.
// The block covers a full 2048-wide context row per step s.
// ---------------------------------------------------------------------------
__device__ __forceinline__ float block_reduce_sum(float val)
{
    __shared__ float sh[8];
    int lane = threadIdx.x & 31, w = threadIdx.x >> 5;
    __syncthreads();
#pragma unroll
    for (int o = 16; o > 0; o >>= 1) val += __shfl_down_sync(0xffffffffu, val, o);
    if (lane == 0) sh[w] = val;
    __syncthreads();
    if (w == 0) {
        val = (lane < 8) ? sh[lane] : 0.f;
#pragma unroll
        for (int o = 4; o > 0; o >>= 1) val += __shfl_down_sync(0xffffffffu, val, o);
        if (lane == 0) sh[0] = val;
    }
    __syncthreads();
    return sh[0];
}

__global__ __launch_bounds__(256)
void scan_final_ln(const float* __restrict__ x, const float* __restrict__ omega,
                   const float* __restrict__ gate, const float* __restrict__ mag,
                   const float* __restrict__ phii, const float* __restrict__ qoff,
                   const float* __restrict__ iscale,
                   const float* __restrict__ gamma, const float* __restrict__ beta,
                   __nv_bfloat16* __restrict__ Ph, __nv_bfloat16* __restrict__ Pl)
{
    const int chunk = blockIdx.x, b = blockIdx.y;
    const int d0 = threadIdx.x * 2;
    float2 is2 = *(const float2*)(iscale + d0);
    const float i0 = fabsf(is2.x), i1 = fabsf(is2.y);
    const int ch = b * Dz + d0;

    float2 phib = *(const float2*)&g_sphi[chunk * NCHAN + ch];
    float2 mr   = *(const float2*)&g_smr [chunk * NCHAN + ch];
    float2 mi   = *(const float2*)&g_smi [chunk * NCHAN + ch];
    float2 cm   = *(const float2*)&g_sm  [chunk * NCHAN + ch];

    // hoist gamma/beta (cols j*512 + d0, j*512 + d0 + 1)
    float2 gg[4], bb[4];
#pragma unroll
    for (int j = 0; j < 4; j++) {
        gg[j] = *(const float2*)(gamma + j * Dz + d0);
        bb[j] = *(const float2*)(beta  + j * Dz + d0);
    }

    size_t idx = ((size_t)b * Sz + (size_t)chunk * SLEN) * Dz + d0;
    int row = b * Sz + chunk * SLEN;
    float pc0 = 0.f, pc1 = 0.f;

    for (int s = 0; s < SLEN; ++s, ++row, idx += Dz) {
        float2 g  = *(const float2*)(gate + idx);
        float2 o  = *(const float2*)(omega + idx);
        float2 m  = *(const float2*)(mag + idx);
        float2 xv = *(const float2*)(x + idx);
        float2 pv = *(const float2*)(phii + idx);
        float2 qv = *(const float2*)(qoff + idx);

        float v[2][4];
        // channel 0
        {
            pc0 += g.x * o.x * i0;
            float phi = pv.x + phib.x + pc0;
            float c, sn; __sincosf(phi, &sn, &c);
            float wc = m.x * xv.x;
            mr.x += wc * c;  mi.x += wc * sn;  cm.x += m.x;
            float r = rsqrtf(cm.x + 1e-8f);
            float mrn = mr.x * r, min_ = mi.x * r;
            float cq, sq; __sincosf(phi + qv.x, &sq, &cq);
            v[0][0] = xv.x * c;  v[0][1] = xv.x * sn;
            v[0][2] = mrn * cq + min_ * sq;  v[0][3] = min_ * cq - mrn * sq;
        }
        // channel 1
        {
            pc1 += g.y * o.y * i1;
            float phi = pv.y + phib.y + pc1;
            float c, sn; __sincosf(phi, &sn, &c);
            float wc = m.y * xv.y;
            mr.y += wc * c;  mi.y += wc * sn;  cm.y += m.y;
            float r = rsqrtf(cm.y + 1e-8f);
            float mrn = mr.y * r, min_ = mi.y * r;
            float cq, sq; __sincosf(phi + qv.y, &sq, &cq);
            v[1][0] = xv.y * c;  v[1][1] = xv.y * sn;
            v[1][2] = mrn * cq + min_ * sq;  v[1][3] = min_ * cq - mrn * sq;
        }

        // LayerNorm over the 2048-wide row (held across the block)
        float part = 0.f;
#pragma unroll
        for (int j = 0; j < 4; j++) part += v[0][j] + v[1][j];
        float mean = block_reduce_sum(part) * (1.0f / (float)D4);

        float sqp = 0.f;
#pragma unroll
        for (int j = 0; j < 4; j++) {
            float a0 = v[0][j] - mean, a1 = v[1][j] - mean;
            sqp += a0 * a0 + a1 * a1;
        }
        float rstd = rsqrtf(block_reduce_sum(sqp) * (1.0f / (float)D4) + 1e-5f);

        const size_t blkrow = (size_t)(row >> 7) * (D4 >> 6);
        const uint32_t rsw = (uint32_t)((row & 127) * 128);
#pragma unroll
        for (int j = 0; j < 4; j++) {
            float y0 = (v[0][j] - mean) * rstd * gg[j].x + bb[j].x;
            float y1 = (v[1][j] - mean) * rstd * gg[j].y + bb[j].y;
            __nv_bfloat16 h0 = __float2bfloat16(y0);
            __nv_bfloat16 h1 = __float2bfloat16(y1);
            __nv_bfloat16 l0 = __float2bfloat16(y0 - __bfloat162float(h0));
            __nv_bfloat16 l1 = __float2bfloat16(y1 - __bfloat162float(h1));
            uint32_t hp = ((uint32_t)__bfloat16_as_ushort(h1) << 16) | __bfloat16_as_ushort(h0);
            uint32_t lp = ((uint32_t)__bfloat16_as_ushort(l1) << 16) | __bfloat16_as_ushort(l0);
            const int col = j * Dz + d0;
            size_t blk = blkrow + (col >> 6);
            uint32_t sw = sw128(rsw + (uint32_t)((col & 63) * 2));
            size_t off = blk * 16384 + sw;
            *(uint32_t*)((char*)Ph + off) = hp;
            *(uint32_t*)((char*)Pl + off) = lp;
        }
    }
}

// ---------------------------------------------------------------------------
// launch
// ---------------------------------------------------------------------------
static inline void* sym(const void* s) { void* p = nullptr; cudaGetSymbolAddress(&p, s); return p; }

extern "C" void kernel_launch(void* const* d_in, const int* in_sizes, int n_in,
                              void* d_out, int out_size)
{
    const float* x       = (const float*)d_in[0];
    const float* W_omega = (const float*)d_in[1];
    const float* b_omega = (const float*)d_in[2];
    const float* W_p1    = (const float*)d_in[3];
    const float* b_p1    = (const float*)d_in[4];
    const float* W_p2    = (const float*)d_in[5];
    const float* b_p2    = (const float*)d_in[6];
    const float* W_gate  = (const float*)d_in[7];
    const float* b_gate  = (const float*)d_in[8];
    const float* iscale  = (const float*)d_in[9];
    const float* W_mag   = (const float*)d_in[10];
    const float* b_mag   = (const float*)d_in[11];
    const float* W_qoff  = (const float*)d_in[12];
    const float* b_qoff  = (const float*)d_in[13];
    const float* ln_g    = (const float*)d_in[14];
    const float* ln_b    = (const float*)d_in[15];
    const float* W_o1    = (const float*)d_in[16];
    const float* b_o1    = (const float*)d_in[17];
    const float* W_o2    = (const float*)d_in[18];
    const float* b_o2    = (const float*)d_in[19];
    float* out = (float*)d_out;

    float* p_omega = (float*)sym(g_omega);
    float* p_mag   = (float*)sym(g_mag);
    float* p_gate  = (float*)sym(g_gate);
    float* p_qoff  = (float*)sym(g_qoff);
    float* p_phii  = (float*)sym(g_phii);

    __nv_bfloat16* xp_h  = (__nv_bfloat16*)sym(g_xp_h);
    __nv_bfloat16* xp_l  = (__nv_bfloat16*)sym(g_xp_l);
    __nv_bfloat16* p1p_h = (__nv_bfloat16*)sym(g_p1p_h);
    __nv_bfloat16* p1p_l = (__nv_bfloat16*)sym(g_p1p_l);
    __nv_bfloat16* cxp_h = (__nv_bfloat16*)sym(g_ctxp_h);
    __nv_bfloat16* cxp_l = (__nv_bfloat16*)sym(g_ctxp_l);
    __nv_bfloat16* hp_h  = (__nv_bfloat16*)sym(g_hp_h);
    __nv_bfloat16* hp_l  = (__nv_bfloat16*)sym(g_hp_l);

    __nv_bfloat16* wom_h = (__nv_bfloat16*)sym(g_wom_h); __nv_bfloat16* wom_l = (__nv_bfloat16*)sym(g_wom_l);
    __nv_bfloat16* wp1_h = (__nv_bfloat16*)sym(g_wp1_h); __nv_bfloat16* wp1_l = (__nv_bfloat16*)sym(g_wp1_l);
    __nv_bfloat16* wp2_h = (__nv_bfloat16*)sym(g_wp2_h); __nv_bfloat16* wp2_l = (__nv_bfloat16*)sym(g_wp2_l);
    __nv_bfloat16* wgt_h = (__nv_bfloat16*)sym(g_wgt_h); __nv_bfloat16* wgt_l = (__nv_bfloat16*)sym(g_wgt_l);
    __nv_bfloat16* wmg_h = (__nv_bfloat16*)sym(g_wmg_h); __nv_bfloat16* wmg_l = (__nv_bfloat16*)sym(g_wmg_l);
    __nv_bfloat16* wqo_h = (__nv_bfloat16*)sym(g_wqo_h); __nv_bfloat16* wqo_l = (__nv_bfloat16*)sym(g_wqo_l);
    __nv_bfloat16* wo1_h = (__nv_bfloat16*)sym(g_wo1_h); __nv_bfloat16* wo1_l = (__nv_bfloat16*)sym(g_wo1_l);
    __nv_bfloat16* wo2_h = (__nv_bfloat16*)sym(g_wo2_h); __nv_bfloat16* wo2_l = (__nv_bfloat16*)sym(g_wo2_l);

    cudaFuncSetAttribute(gemm_mma<0,0>, cudaFuncAttributeMaxDynamicSharedMemorySize, GEMM_SMEM);
    cudaFuncSetAttribute(gemm_mma<1,1>, cudaFuncAttributeMaxDynamicSharedMemorySize, GEMM_SMEM);
    cudaFuncSetAttribute(gemm_mma<2,0>, cudaFuncAttributeMaxDynamicSharedMemorySize, GEMM_SMEM);
    cudaFuncSetAttribute(gemm_mma<3,0>, cudaFuncAttributeMaxDynamicSharedMemorySize, GEMM_SMEM);
    cudaFuncSetAttribute(gemm_mma<4,0>, cudaFuncAttributeMaxDynamicSharedMemorySize, GEMM_SMEM);

    // --- pack weights ---
    {
        long t = (long)Dz * (Dz >> 3);
        int blks = (int)((t + 255) / 256);
        pack_w_kernel<<<blks, 256>>>(W_omega, wom_h, wom_l, Dz, Dz);
        pack_w_kernel<<<blks, 256>>>(W_p1,    wp1_h, wp1_l, Dz, Dz);
        pack_w_kernel<<<blks, 256>>>(W_p2,    wp2_h, wp2_l, Dz, Dz);
        pack_w_kernel<<<blks, 256>>>(W_gate,  wgt_h, wgt_l, Dz, Dz);
        pack_w_kernel<<<blks, 256>>>(W_mag,   wmg_h, wmg_l, Dz, Dz);
        pack_w_kernel<<<blks, 256>>>(W_qoff,  wqo_h, wqo_l, Dz, Dz);
        long t1 = (long)D2 * (D4 >> 3);
        pack_w_kernel<<<(int)((t1 + 255) / 256), 256>>>(W_o1, wo1_h, wo1_l, D4, D2);
        long t2 = (long)Dz * (D2 >> 3);
        pack_w_kernel<<<(int)((t2 + 255) / 256), 256>>>(W_o2, wo2_h, wo2_l, D2, Dz);
    }

    // --- pack x ---
    {
        long t = (long)Mz * Dz / 8;
        pack_a_kernel<<<(int)((t + 255) / 256), 256>>>(x, xp_h, xp_l, Dz, t);
    }

    dim3 blk(256);
    dim3 grdD(Dz / 256, Mz / 128);   // (2, 256)
    dim3 grd2(D2 / 256, Mz / 128);   // (4, 256)

    // projections
    gemm_mma<0,0><<<grdD, blk, GEMM_SMEM>>>(xp_h, xp_l, wom_h, wom_l, b_omega, p_omega, nullptr, nullptr, nullptr, Dz, Dz);
    gemm_mma<3,0><<<grdD, blk, GEMM_SMEM>>>(xp_h, xp_l, wmg_h, wmg_l, b_mag,   p_mag,   nullptr, nullptr, nullptr, Dz, Dz);
    gemm_mma<2,0><<<grdD, blk, GEMM_SMEM>>>(xp_h, xp_l, wgt_h, wgt_l, b_gate,  p_gate,  nullptr, nullptr, nullptr, Dz, Dz);
    gemm_mma<0,0><<<grdD, blk, GEMM_SMEM>>>(xp_h, xp_l, wqo_h, wqo_l, b_qoff,  p_qoff,  nullptr, nullptr, nullptr, Dz, Dz);
    gemm_mma<1,1><<<grdD, blk, GEMM_SMEM>>>(xp_h, xp_l, wp1_h, wp1_l, b_p1,    nullptr, p1p_h,   p1p_l,   nullptr, Dz, Dz);
    gemm_mma<0,0><<<grdD, blk, GEMM_SMEM>>>(p1p_h, p1p_l, wp2_h, wp2_l, b_p2,  p_phii,  nullptr, nullptr, nullptr, Dz, Dz);

    // parallel scan + fused LN/pack -> packed ctx
    dim3 sgrid(SCH, Bz);
    scan_sum1<<<sgrid, 256>>>(p_omega, p_gate, p_mag, iscale);
    scan_pfx1<<<NCHAN / 256, 256>>>();
    scan_sum2<<<sgrid, 256>>>(x, p_omega, p_gate, p_mag, p_phii, iscale);
    scan_pfx2<<<NCHAN / 256, 256>>>();
    scan_final_ln<<<sgrid, 256>>>(x, p_omega, p_gate, p_mag, p_phii, p_qoff, iscale,
                                  ln_g, ln_b, cxp_h, cxp_l);

    // output MLP
    gemm_mma<1,1><<<grd2, blk, GEMM_SMEM>>>(cxp_h, cxp_l, wo1_h, wo1_l, b_o1, nullptr, hp_h, hp_l, nullptr, D2, D4);
    gemm_mma<4,0><<<grdD, blk, GEMM_SMEM>>>(hp_h, hp_l, wo2_h, wo2_l, b_o2, out, nullptr, nullptr, x, Dz, D2);
}